// round 1
// baseline (speedup 1.0000x reference)
#include <cuda_runtime.h>
#include <math.h>

#define Bn 4
#define Tn 4096
#define Cn 1024
#define Hn 64

// Scratch for projected q, k, v (no cudaMalloc allowed)
__device__ float g_q[Bn * Tn * Hn];
__device__ float g_k[Bn * Tn * Hn];
__device__ float g_v[Bn * Tn * Hn];

#define PROJ_SMEM (64 * 68 * 4 + 3 * 64 * 64 * 4)
#define ATTN_SMEM (4 * 64 * 68 * 4 + 3 * 64 * 4)

// ---------------------------------------------------------------------------
// Projection: y = x @ W for W in {Wq, Wk, Wv}.  M=16384, N=64, K=1024.
// Block: 64 rows of x, all 192 output cols.  256 threads, 4x4 micro-tiles.
// ---------------------------------------------------------------------------
__global__ __launch_bounds__(256) void proj_kernel(
    const float* __restrict__ x,
    const float* __restrict__ Wq,
    const float* __restrict__ Wk,
    const float* __restrict__ Wv)
{
    extern __shared__ float sm[];
    float* xs = sm;             // [64][68]   xs[kk*68 + r]  (transposed x tile)
    float* ws = sm + 64 * 68;   // [3][64][64] ws[w*4096 + kk*64 + c]

    const int tid = threadIdx.x;
    const int m0 = blockIdx.x * 64;
    const int tr = (tid >> 4) * 4;
    const int tc = (tid & 15) * 4;

    float acc[3][4][4];
#pragma unroll
    for (int w = 0; w < 3; w++)
#pragma unroll
        for (int i = 0; i < 4; i++)
#pragma unroll
            for (int jj = 0; jj < 4; jj++) acc[w][i][jj] = 0.f;

    for (int k0 = 0; k0 < Cn; k0 += 64) {
        __syncthreads();
        for (int idx = tid; idx < 64 * 64; idx += 256) {
            int r = idx >> 6, c = idx & 63;
            xs[c * 68 + r] = x[(size_t)(m0 + r) * Cn + k0 + c];
            int krow = (k0 + r) * 64;   // here r plays the role of kk
            ws[0 * 4096 + idx] = Wq[krow + c];
            ws[1 * 4096 + idx] = Wk[krow + c];
            ws[2 * 4096 + idx] = Wv[krow + c];
        }
        __syncthreads();

#pragma unroll 8
        for (int kk = 0; kk < 64; kk++) {
            float4 a4 = *(const float4*)&xs[kk * 68 + tr];
            float a[4] = {a4.x, a4.y, a4.z, a4.w};
#pragma unroll
            for (int w = 0; w < 3; w++) {
                float4 b4 = *(const float4*)&ws[w * 4096 + kk * 64 + tc];
                float b[4] = {b4.x, b4.y, b4.z, b4.w};
#pragma unroll
                for (int i = 0; i < 4; i++)
#pragma unroll
                    for (int jj = 0; jj < 4; jj++)
                        acc[w][i][jj] += a[i] * b[jj];
            }
        }
    }

    float* outp0 = g_q;
    float* outp1 = g_k;
    float* outp2 = g_v;
#pragma unroll
    for (int i = 0; i < 4; i++) {
        size_t row = (size_t)(m0 + tr + i) * 64 + tc;
        *(float4*)&outp0[row] = make_float4(acc[0][i][0], acc[0][i][1], acc[0][i][2], acc[0][i][3]);
        *(float4*)&outp1[row] = make_float4(acc[1][i][0], acc[1][i][1], acc[1][i][2], acc[1][i][3]);
        *(float4*)&outp2[row] = make_float4(acc[2][i][0], acc[2][i][1], acc[2][i][2], acc[2][i][3]);
    }
}

// ---------------------------------------------------------------------------
// Causal flash attention.  Block = (batch b, query tile of 64 rows).
// Online softmax, fp32 accumulation.  256 threads, 4x4 micro-tiles.
// ---------------------------------------------------------------------------
__global__ __launch_bounds__(256) void attn_kernel(float* __restrict__ out)
{
    extern __shared__ float sm[];
    float* qs = sm;                 // [64][68]  qs[h*68 + r]
    float* ks = sm + 64 * 68;       // [64][68]  ks[h*68 + c]
    float* vs = sm + 2 * 64 * 68;   // [64][68]  vs[s*68 + c]
    float* ps = sm + 3 * 64 * 68;   // [64][68]  ps[r*68 + c]
    float* mrow = sm + 4 * 64 * 68; // [64]
    float* lrow = mrow + 64;        // [64]
    float* crow = lrow + 64;        // [64]

    const int tid = threadIdx.x;
    const int b = blockIdx.y;
    const int qt = gridDim.x - 1 - blockIdx.x;  // longest blocks first
    const int tr = (tid >> 4) * 4;
    const int tc = (tid & 15) * 4;
    const size_t base = (size_t)b * Tn * Hn;

    if (tid < 64) { mrow[tid] = -3.0e38f; lrow[tid] = 0.f; }

    // Load Q tile transposed: qs[h][r]
    for (int idx = tid; idx < 64 * 64; idx += 256) {
        int r = idx >> 6, h = idx & 63;
        qs[h * 68 + r] = g_q[base + (size_t)(qt * 64 + r) * 64 + h];
    }

    float o[4][4];
#pragma unroll
    for (int i = 0; i < 4; i++)
#pragma unroll
        for (int jj = 0; jj < 4; jj++) o[i][jj] = 0.f;

    __syncthreads();

    for (int j = 0; j <= qt; j++) {
        // Load K tile (transposed) and V tile
        for (int idx = tid; idx < 64 * 64; idx += 256) {
            int r = idx >> 6, h = idx & 63;
            float kvk = g_k[base + (size_t)(j * 64 + r) * 64 + h];
            float kvv = g_v[base + (size_t)(j * 64 + r) * 64 + h];
            ks[h * 68 + r] = kvk;
            vs[r * 68 + h] = kvv;
        }
        __syncthreads();

        // S = Q K^T  (64x64 tile)
        float s_acc[4][4];
#pragma unroll
        for (int i = 0; i < 4; i++)
#pragma unroll
            for (int jj = 0; jj < 4; jj++) s_acc[i][jj] = 0.f;

#pragma unroll 8
        for (int h = 0; h < 64; h++) {
            float4 a4 = *(const float4*)&qs[h * 68 + tr];
            float4 b4 = *(const float4*)&ks[h * 68 + tc];
            float a[4] = {a4.x, a4.y, a4.z, a4.w};
            float bb[4] = {b4.x, b4.y, b4.z, b4.w};
#pragma unroll
            for (int i = 0; i < 4; i++)
#pragma unroll
                for (int jj = 0; jj < 4; jj++)
                    s_acc[i][jj] += a[i] * bb[jj];
        }
#pragma unroll
        for (int i = 0; i < 4; i++)
#pragma unroll
            for (int jj = 0; jj < 4; jj++)
                ps[(tr + i) * 68 + tc + jj] = s_acc[i][jj] * 0.125f;
        __syncthreads();

        // Per-row online softmax (one thread per row)
        if (tid < 64) {
            const int r = tid;
            const int cmax = (j == qt) ? r : 63;
            float mold = mrow[r];
            float mx = mold;
            for (int c = 0; c <= cmax; c++) mx = fmaxf(mx, ps[r * 68 + c]);
            float corr = __expf(mold - mx);
            float sum = 0.f;
            for (int c = 0; c < 64; c++) {
                float p = (c <= cmax) ? __expf(ps[r * 68 + c] - mx) : 0.f;
                ps[r * 68 + c] = p;
                sum += p;
            }
            mrow[r] = mx;
            crow[r] = corr;
            lrow[r] = lrow[r] * corr + sum;
        }
        __syncthreads();

        // Rescale existing accumulator, then O += P @ V
        float c0 = crow[tr + 0], c1 = crow[tr + 1], c2 = crow[tr + 2], c3 = crow[tr + 3];
#pragma unroll
        for (int jj = 0; jj < 4; jj++) {
            o[0][jj] *= c0; o[1][jj] *= c1; o[2][jj] *= c2; o[3][jj] *= c3;
        }

#pragma unroll 8
        for (int s = 0; s < 64; s++) {
            float4 v4 = *(const float4*)&vs[s * 68 + tc];
            float vv[4] = {v4.x, v4.y, v4.z, v4.w};
            float p0 = ps[(tr + 0) * 68 + s];
            float p1 = ps[(tr + 1) * 68 + s];
            float p2 = ps[(tr + 2) * 68 + s];
            float p3 = ps[(tr + 3) * 68 + s];
#pragma unroll
            for (int jj = 0; jj < 4; jj++) {
                o[0][jj] += p0 * vv[jj];
                o[1][jj] += p1 * vv[jj];
                o[2][jj] += p2 * vv[jj];
                o[3][jj] += p3 * vv[jj];
            }
        }
        __syncthreads();
    }

    // Epilogue: normalize and store
    float inv0 = 1.f / lrow[tr + 0];
    float inv1 = 1.f / lrow[tr + 1];
    float inv2 = 1.f / lrow[tr + 2];
    float inv3 = 1.f / lrow[tr + 3];
    float inv[4] = {inv0, inv1, inv2, inv3};
#pragma unroll
    for (int i = 0; i < 4; i++) {
        size_t row = base + (size_t)(qt * 64 + tr + i) * 64 + tc;
        *(float4*)&out[row] = make_float4(o[i][0] * inv[i], o[i][1] * inv[i],
                                          o[i][2] * inv[i], o[i][3] * inv[i]);
    }
}

// ---------------------------------------------------------------------------
extern "C" void kernel_launch(void* const* d_in, const int* in_sizes, int n_in,
                              void* d_out, int out_size)
{
    const float* x  = (const float*)d_in[0];
    const float* Wk = (const float*)d_in[1];
    const float* Wq = (const float*)d_in[2];
    const float* Wv = (const float*)d_in[3];
    float* out = (float*)d_out;

    cudaFuncSetAttribute(proj_kernel, cudaFuncAttributeMaxDynamicSharedMemorySize, PROJ_SMEM);
    cudaFuncSetAttribute(attn_kernel, cudaFuncAttributeMaxDynamicSharedMemorySize, ATTN_SMEM);

    proj_kernel<<<(Bn * Tn) / 64, 256, PROJ_SMEM>>>(x, Wq, Wk, Wv);
    attn_kernel<<<dim3(Tn / 64, Bn), 256, ATTN_SMEM>>>(out);
}

// round 2
// speedup vs baseline: 2.4528x; 2.4528x over previous
#include <cuda_runtime.h>
#include <cstdint>

#define Bn 4
#define Tn 4096
#define Cn 1024
#define Hn 64

// Scratch for projected q, k, v (no cudaMalloc allowed)
__device__ float g_q[Bn * Tn * Hn];
__device__ float g_k[Bn * Tn * Hn];
__device__ float g_v[Bn * Tn * Hn];

__device__ __forceinline__ uint32_t f2tf(float f) {
    uint32_t r;
    asm("cvt.rna.tf32.f32 %0, %1;" : "=r"(r) : "f"(f));
    return r;
}

__device__ __forceinline__ void mma8(float* c, const uint32_t* a, const uint32_t* b) {
    asm volatile(
        "mma.sync.aligned.m16n8k8.row.col.f32.tf32.tf32.f32 "
        "{%0,%1,%2,%3}, {%4,%5,%6,%7}, {%8,%9}, {%0,%1,%2,%3};"
        : "+f"(c[0]), "+f"(c[1]), "+f"(c[2]), "+f"(c[3])
        : "r"(a[0]), "r"(a[1]), "r"(a[2]), "r"(a[3]), "r"(b[0]), "r"(b[1]));
}

// ---------------------------------------------------------------------------
// Projection: y = x @ {Wq,Wk,Wv}. M=16384, K=1024, N=192 (3x64).
// Block = 64 rows, 256 threads (8 warps). Warp w owns cols [24w, 24w+24).
// tf32 mma m16n8k8. K-chunk = 32.
// ---------------------------------------------------------------------------
#define PJ_SMEM ((64 * 36 + 32 * 200) * 4)

__global__ __launch_bounds__(256, 1) void proj_kernel(
    const float* __restrict__ x,
    const float* __restrict__ Wq,
    const float* __restrict__ Wk,
    const float* __restrict__ Wv)
{
    extern __shared__ uint32_t sm[];
    uint32_t* xs = sm;           // [64][36] tf32, xs[row][k]
    uint32_t* ws = sm + 64 * 36; // [32][200] tf32, ws[k][col 0..191]

    const int tid = threadIdx.x;
    const int lane = tid & 31, wid = tid >> 5;
    const int m0 = blockIdx.x * 64;
    const int g = lane >> 2, q4 = lane & 3;

    float acc[4][3][4];
#pragma unroll
    for (int mt = 0; mt < 4; mt++)
#pragma unroll
        for (int nt = 0; nt < 3; nt++)
#pragma unroll
            for (int i = 0; i < 4; i++) acc[mt][nt][i] = 0.f;

    for (int k0 = 0; k0 < Cn; k0 += 32) {
        __syncthreads();
        // load x tile: 64x32
#pragma unroll
        for (int i = 0; i < 2; i++) {
            int idx = tid + i * 256;
            int r = idx >> 3, c4 = (idx & 7) * 4;
            float4 v = *(const float4*)&x[(size_t)(m0 + r) * Cn + k0 + c4];
            uint32_t* d = &xs[r * 36 + c4];
            d[0] = f2tf(v.x); d[1] = f2tf(v.y); d[2] = f2tf(v.z); d[3] = f2tf(v.w);
        }
        // load W tiles: 32 x 192 (cols 0-63 Wq, 64-127 Wk, 128-191 Wv)
#pragma unroll
        for (int i = 0; i < 6; i++) {
            int idx = tid + i * 256;
            int kk = idx / 48, c4 = (idx % 48) * 4;
            const float* srcp = (c4 < 64) ? Wq : (c4 < 128) ? Wk : Wv;
            float4 v = *(const float4*)&srcp[(size_t)(k0 + kk) * 64 + (c4 & 63)];
            uint32_t* d = &ws[kk * 200 + c4];
            d[0] = f2tf(v.x); d[1] = f2tf(v.y); d[2] = f2tf(v.z); d[3] = f2tf(v.w);
        }
        __syncthreads();

#pragma unroll
        for (int ksx = 0; ksx < 4; ksx++) {
            int kk = ksx * 8 + q4;
            uint32_t bfr[3][2];
#pragma unroll
            for (int nt = 0; nt < 3; nt++) {
                int n = wid * 24 + nt * 8 + g;
                bfr[nt][0] = ws[kk * 200 + n];
                bfr[nt][1] = ws[(kk + 4) * 200 + n];
            }
#pragma unroll
            for (int mt = 0; mt < 4; mt++) {
                int r = mt * 16 + g;
                uint32_t a[4] = { xs[r * 36 + kk], xs[(r + 8) * 36 + kk],
                                  xs[r * 36 + kk + 4], xs[(r + 8) * 36 + kk + 4] };
#pragma unroll
                for (int nt = 0; nt < 3; nt++) mma8(acc[mt][nt], a, bfr[nt]);
            }
        }
    }

#pragma unroll
    for (int mt = 0; mt < 4; mt++)
#pragma unroll
        for (int nt = 0; nt < 3; nt++) {
            int col = wid * 24 + nt * 8;
            float* dst = (col < 64) ? g_q : (col < 128) ? g_k : g_v;
            int h = (col & 63) + 2 * q4;
            size_t r = (size_t)(m0 + mt * 16 + g) * 64 + h;
            *(float2*)&dst[r] = make_float2(acc[mt][nt][0], acc[mt][nt][1]);
            *(float2*)&dst[r + 8 * 64] = make_float2(acc[mt][nt][2], acc[mt][nt][3]);
        }
}

// ---------------------------------------------------------------------------
// Causal flash attention, tf32 mma, 64-row Q tiles.
// Block = 256 threads (8 warps): warp tile 16 rows x 32 cols (wr = row group,
// wc = col half). Each CTA processes the paired q-tiles (p, 63-p): 65 steps.
// ---------------------------------------------------------------------------
#define AT_SMEM ((64 * 68 * 3 + 64 * 72 + 64 * 2 + 128 * 2) * 4)

__global__ __launch_bounds__(256, 1) void attn_kernel(float* __restrict__ out)
{
    extern __shared__ uint32_t sm[];
    uint32_t* qs = sm;                   // [64][68] tf32 Q (pre-scaled by 1/8)
    uint32_t* ks_ = sm + 4352;           // [64][68] tf32 K  (ks_[key][h])
    uint32_t* ps = sm + 2 * 4352;        // [64][68] tf32 P
    uint32_t* vs = sm + 3 * 4352;        // [64][72] tf32 V  (vs[key][h])
    float* msh  = (float*)(sm + 3 * 4352 + 64 * 72); // [64]
    float* lsh  = msh + 64;                           // [64]
    float* pmax = lsh + 64;                           // [2][64]
    float* psum = pmax + 128;                         // [2][64]

    const int tid = threadIdx.x, lane = tid & 31, wid = tid >> 5;
    const int wc = wid >> 2, wr = wid & 3;
    const int g = lane >> 2, q4 = lane & 3;
    const int mrow = wr * 16 + g;
    const size_t base = (size_t)blockIdx.y * Tn * Hn;

    for (int pass = 0; pass < 2; pass++) {
        const int qt = pass ? (63 - (int)blockIdx.x) : (int)blockIdx.x;
        __syncthreads();  // prior pass fully done before touching smem state
        if (tid < 64) { msh[tid] = -1e30f; lsh[tid] = 0.f; }
        // load Q tile (scaled by H^-0.5 = 0.125)
#pragma unroll
        for (int i = 0; i < 4; i++) {
            int idx = tid + i * 256;
            int r = idx >> 4, c4 = (idx & 15) * 4;
            float4 v = *(const float4*)&g_q[base + (size_t)(qt * 64 + r) * 64 + c4];
            uint32_t* d = &qs[r * 68 + c4];
            d[0] = f2tf(v.x * 0.125f); d[1] = f2tf(v.y * 0.125f);
            d[2] = f2tf(v.z * 0.125f); d[3] = f2tf(v.w * 0.125f);
        }
        float o[4][4];
#pragma unroll
        for (int nt = 0; nt < 4; nt++)
#pragma unroll
            for (int i = 0; i < 4; i++) o[nt][i] = 0.f;

        for (int j = 0; j <= qt; j++) {
            __syncthreads();  // protect ks/vs/ps reuse; publish Q + stats init
            // load K and V tiles
#pragma unroll
            for (int i = 0; i < 4; i++) {
                int idx = tid + i * 256;
                int r = idx >> 4, c4 = (idx & 15) * 4;
                size_t gofs = base + (size_t)(j * 64 + r) * 64 + c4;
                float4 kv = *(const float4*)&g_k[gofs];
                float4 vv = *(const float4*)&g_v[gofs];
                uint32_t* dk = &ks_[r * 68 + c4];
                dk[0] = f2tf(kv.x); dk[1] = f2tf(kv.y); dk[2] = f2tf(kv.z); dk[3] = f2tf(kv.w);
                uint32_t* dv = &vs[r * 72 + c4];
                dv[0] = f2tf(vv.x); dv[1] = f2tf(vv.y); dv[2] = f2tf(vv.z); dv[3] = f2tf(vv.w);
            }
            __syncthreads();

            // S = (Q/8) K^T  : warp tile 16 x 32
            float s[4][4];
#pragma unroll
            for (int nt = 0; nt < 4; nt++)
#pragma unroll
                for (int i = 0; i < 4; i++) s[nt][i] = 0.f;
#pragma unroll
            for (int ksx = 0; ksx < 8; ksx++) {
                int kk = ksx * 8 + q4;
                uint32_t a[4] = { qs[mrow * 68 + kk], qs[(mrow + 8) * 68 + kk],
                                  qs[mrow * 68 + kk + 4], qs[(mrow + 8) * 68 + kk + 4] };
#pragma unroll
                for (int nt = 0; nt < 4; nt++) {
                    int n = wc * 32 + nt * 8 + g;
                    uint32_t bb[2] = { ks_[n * 68 + kk], ks_[n * 68 + kk + 4] };
                    mma8(s[nt], a, bb);
                }
            }
            // causal mask on the diagonal tile
            if (j == qt) {
#pragma unroll
                for (int nt = 0; nt < 4; nt++) {
                    int c0 = wc * 32 + nt * 8 + 2 * q4;
                    if (c0 > mrow)     s[nt][0] = -1e30f;
                    if (c0 + 1 > mrow) s[nt][1] = -1e30f;
                    if (c0 > mrow + 8)     s[nt][2] = -1e30f;
                    if (c0 + 1 > mrow + 8) s[nt][3] = -1e30f;
                }
            }
            // partial row max over this warp's 32 cols
            float mx0 = -1e30f, mx1 = -1e30f;
#pragma unroll
            for (int nt = 0; nt < 4; nt++) {
                mx0 = fmaxf(mx0, fmaxf(s[nt][0], s[nt][1]));
                mx1 = fmaxf(mx1, fmaxf(s[nt][2], s[nt][3]));
            }
            mx0 = fmaxf(mx0, __shfl_xor_sync(~0u, mx0, 1));
            mx0 = fmaxf(mx0, __shfl_xor_sync(~0u, mx0, 2));
            mx1 = fmaxf(mx1, __shfl_xor_sync(~0u, mx1, 1));
            mx1 = fmaxf(mx1, __shfl_xor_sync(~0u, mx1, 2));
            if (q4 == 0) { pmax[wc * 64 + mrow] = mx0; pmax[wc * 64 + mrow + 8] = mx1; }
            __syncthreads();

            float mold0 = msh[mrow], mold1 = msh[mrow + 8];
            float mn0 = fmaxf(mold0, fmaxf(pmax[mrow], pmax[64 + mrow]));
            float mn1 = fmaxf(mold1, fmaxf(pmax[mrow + 8], pmax[64 + mrow + 8]));
            float corr0 = __expf(mold0 - mn0), corr1 = __expf(mold1 - mn1);
            float sum0 = 0.f, sum1 = 0.f;
#pragma unroll
            for (int nt = 0; nt < 4; nt++) {
                float p0 = __expf(s[nt][0] - mn0), p1 = __expf(s[nt][1] - mn0);
                float p2 = __expf(s[nt][2] - mn1), p3 = __expf(s[nt][3] - mn1);
                sum0 += p0 + p1; sum1 += p2 + p3;
                int c = wc * 32 + nt * 8 + 2 * q4;
                uint2 w0 = make_uint2(f2tf(p0), f2tf(p1));
                *(uint2*)&ps[mrow * 68 + c] = w0;
                uint2 w1 = make_uint2(f2tf(p2), f2tf(p3));
                *(uint2*)&ps[(mrow + 8) * 68 + c] = w1;
            }
            sum0 += __shfl_xor_sync(~0u, sum0, 1); sum0 += __shfl_xor_sync(~0u, sum0, 2);
            sum1 += __shfl_xor_sync(~0u, sum1, 1); sum1 += __shfl_xor_sync(~0u, sum1, 2);
            if (q4 == 0) { psum[wc * 64 + mrow] = sum0; psum[wc * 64 + mrow + 8] = sum1; }
            __syncthreads();

            if (wc == 0 && q4 == 0) {
                lsh[mrow] = lsh[mrow] * corr0 + psum[mrow] + psum[64 + mrow];
                lsh[mrow + 8] = lsh[mrow + 8] * corr1 + psum[mrow + 8] + psum[64 + mrow + 8];
                msh[mrow] = mn0; msh[mrow + 8] = mn1;
            }
            // rescale O, then O += P V  (P re-read from smem: full 64-col rows)
#pragma unroll
            for (int nt = 0; nt < 4; nt++) {
                o[nt][0] *= corr0; o[nt][1] *= corr0;
                o[nt][2] *= corr1; o[nt][3] *= corr1;
            }
#pragma unroll
            for (int ksx = 0; ksx < 8; ksx++) {
                int kk = ksx * 8 + q4;
                uint32_t a[4] = { ps[mrow * 68 + kk], ps[(mrow + 8) * 68 + kk],
                                  ps[mrow * 68 + kk + 4], ps[(mrow + 8) * 68 + kk + 4] };
#pragma unroll
                for (int nt = 0; nt < 4; nt++) {
                    int h = wc * 32 + nt * 8 + g;
                    uint32_t bb[2] = { vs[kk * 72 + h], vs[(kk + 4) * 72 + h] };
                    mma8(o[nt], a, bb);
                }
            }
        }
        __syncthreads();
        float li0 = 1.f / lsh[mrow], li1 = 1.f / lsh[mrow + 8];
#pragma unroll
        for (int nt = 0; nt < 4; nt++) {
            int c = wc * 32 + nt * 8 + 2 * q4;
            size_t r0 = base + (size_t)(qt * 64 + mrow) * 64 + c;
            *(float2*)&out[r0] = make_float2(o[nt][0] * li0, o[nt][1] * li0);
            *(float2*)&out[r0 + 8 * 64] = make_float2(o[nt][2] * li1, o[nt][3] * li1);
        }
    }
}

// ---------------------------------------------------------------------------
extern "C" void kernel_launch(void* const* d_in, const int* in_sizes, int n_in,
                              void* d_out, int out_size)
{
    const float* x  = (const float*)d_in[0];
    const float* Wk = (const float*)d_in[1];
    const float* Wq = (const float*)d_in[2];
    const float* Wv = (const float*)d_in[3];
    float* out = (float*)d_out;

    cudaFuncSetAttribute(proj_kernel, cudaFuncAttributeMaxDynamicSharedMemorySize, PJ_SMEM);
    cudaFuncSetAttribute(attn_kernel, cudaFuncAttributeMaxDynamicSharedMemorySize, AT_SMEM);

    proj_kernel<<<(Bn * Tn) / 64, 256, PJ_SMEM>>>(x, Wq, Wk, Wv);
    attn_kernel<<<dim3(Tn / 64, Bn), 256, AT_SMEM>>>(out);
}

// round 3
// speedup vs baseline: 4.2185x; 1.7199x over previous
#include <cuda_runtime.h>
#include <cstdint>

#define Bn 4
#define Tn 4096
#define Cn 1024
#define Hn 64

// Scratch for projected q, k, v — stored as tf32-rounded fp32 bit patterns.
// g_q additionally pre-scaled by H^-0.5 = 0.125.
__device__ float g_q[Bn * Tn * Hn];
__device__ float g_k[Bn * Tn * Hn];
__device__ float g_v[Bn * Tn * Hn];

__device__ __forceinline__ uint32_t f2tf(float f) {
    uint32_t r;
    asm("cvt.rna.tf32.f32 %0, %1;" : "=r"(r) : "f"(f));
    return r;
}

__device__ __forceinline__ void mma8(float* c, const uint32_t* a, const uint32_t* b) {
    asm volatile(
        "mma.sync.aligned.m16n8k8.row.col.f32.tf32.tf32.f32 "
        "{%0,%1,%2,%3}, {%4,%5,%6,%7}, {%8,%9}, {%0,%1,%2,%3};"
        : "+f"(c[0]), "+f"(c[1]), "+f"(c[2]), "+f"(c[3])
        : "r"(a[0]), "r"(a[1]), "r"(a[2]), "r"(a[3]), "r"(b[0]), "r"(b[1]));
}

__device__ __forceinline__ void cpa16(void* dst, const void* src) {
    uint32_t d = (uint32_t)__cvta_generic_to_shared(dst);
    asm volatile("cp.async.cg.shared.global [%0], [%1], 16;" :: "r"(d), "l"(src));
}
#define CP_COMMIT() asm volatile("cp.async.commit_group;")
#define CP_WAIT0()  asm volatile("cp.async.wait_group 0;")

// ---------------------------------------------------------------------------
// Projection: y = x @ {Wq,Wk,Wv}. M=16384, K=1024, N=192 (3x64).
// Block = 64 rows, 256 threads (8 warps). Warp w owns cols [24w, 24w+24).
// Outputs written tf32-rounded (q pre-scaled by 0.125).
// ---------------------------------------------------------------------------
#define PJ_SMEM ((64 * 36 + 32 * 200) * 4)

__global__ __launch_bounds__(256, 2) void proj_kernel(
    const float* __restrict__ x,
    const float* __restrict__ Wq,
    const float* __restrict__ Wk,
    const float* __restrict__ Wv)
{
    extern __shared__ uint32_t sm[];
    uint32_t* xs = sm;           // [64][36] tf32, xs[row][k]
    uint32_t* ws = sm + 64 * 36; // [32][200] tf32, ws[k][col 0..191]

    const int tid = threadIdx.x;
    const int lane = tid & 31, wid = tid >> 5;
    const int m0 = blockIdx.x * 64;
    const int g = lane >> 2, q4 = lane & 3;

    float acc[4][3][4];
#pragma unroll
    for (int mt = 0; mt < 4; mt++)
#pragma unroll
        for (int nt = 0; nt < 3; nt++)
#pragma unroll
            for (int i = 0; i < 4; i++) acc[mt][nt][i] = 0.f;

    for (int k0 = 0; k0 < Cn; k0 += 32) {
        __syncthreads();
#pragma unroll
        for (int i = 0; i < 2; i++) {
            int idx = tid + i * 256;
            int r = idx >> 3, c4 = (idx & 7) * 4;
            float4 v = *(const float4*)&x[(size_t)(m0 + r) * Cn + k0 + c4];
            uint32_t* d = &xs[r * 36 + c4];
            d[0] = f2tf(v.x); d[1] = f2tf(v.y); d[2] = f2tf(v.z); d[3] = f2tf(v.w);
        }
#pragma unroll
        for (int i = 0; i < 6; i++) {
            int idx = tid + i * 256;
            int kk = idx / 48, c4 = (idx % 48) * 4;
            const float* srcp = (c4 < 64) ? Wq : (c4 < 128) ? Wk : Wv;
            float4 v = *(const float4*)&srcp[(size_t)(k0 + kk) * 64 + (c4 & 63)];
            uint32_t* d = &ws[kk * 200 + c4];
            d[0] = f2tf(v.x); d[1] = f2tf(v.y); d[2] = f2tf(v.z); d[3] = f2tf(v.w);
        }
        __syncthreads();

#pragma unroll
        for (int ksx = 0; ksx < 4; ksx++) {
            int kk = ksx * 8 + q4;
            uint32_t bfr[3][2];
#pragma unroll
            for (int nt = 0; nt < 3; nt++) {
                int n = wid * 24 + nt * 8 + g;
                bfr[nt][0] = ws[kk * 200 + n];
                bfr[nt][1] = ws[(kk + 4) * 200 + n];
            }
#pragma unroll
            for (int mt = 0; mt < 4; mt++) {
                int r = mt * 16 + g;
                uint32_t a[4] = { xs[r * 36 + kk], xs[(r + 8) * 36 + kk],
                                  xs[r * 36 + kk + 4], xs[(r + 8) * 36 + kk + 4] };
#pragma unroll
                for (int nt = 0; nt < 3; nt++) mma8(acc[mt][nt], a, bfr[nt]);
            }
        }
    }

#pragma unroll
    for (int mt = 0; mt < 4; mt++)
#pragma unroll
        for (int nt = 0; nt < 3; nt++) {
            int col = wid * 24 + nt * 8;
            float* dst = (col < 64) ? g_q : (col < 128) ? g_k : g_v;
            float sc = (col < 64) ? 0.125f : 1.0f;
            int h = (col & 63) + 2 * q4;
            size_t r = (size_t)(m0 + mt * 16 + g) * 64 + h;
            uint2 w0 = make_uint2(f2tf(acc[mt][nt][0] * sc), f2tf(acc[mt][nt][1] * sc));
            uint2 w1 = make_uint2(f2tf(acc[mt][nt][2] * sc), f2tf(acc[mt][nt][3] * sc));
            *(uint2*)&dst[r] = w0;
            *(uint2*)&dst[r + 8 * 64] = w1;
        }
}

// ---------------------------------------------------------------------------
// Causal flash attention, tf32 mma, 64-row Q tiles, paired scheduling.
// grid (32, 4): CTA p handles q-tiles p and 63-p => exactly 65 KV steps each.
// 8 warps: 4 row-groups x 2 col-halves, warp tile 16x32.
// K/V tiles double-buffered via cp.async (data pre-converted to tf32 in proj).
// ---------------------------------------------------------------------------
#define AT_SMEM ((64 * 68 * 2 + 2 * 64 * 68 + 2 * 64 * 72 + 384) * 4)

__global__ __launch_bounds__(256, 1) void attn_kernel(float* __restrict__ out)
{
    extern __shared__ uint32_t sm[];
    uint32_t* qs = sm;                    // [64][68] tf32 Q (pre-scaled)
    uint32_t* ps = sm + 4352;             // [64][68] tf32 P
    uint32_t* ks_ = sm + 2 * 4352;        // 2 x [64][68] tf32 K
    uint32_t* vs = sm + 4 * 4352;         // 2 x [64][72] tf32 V
    float* msh  = (float*)(sm + 4 * 4352 + 2 * 4608); // [64]
    float* lsh  = msh + 64;                            // [64]
    float* pmax = lsh + 64;                            // [2][64]
    float* psum = pmax + 128;                          // [2][64]

    const int tid = threadIdx.x, lane = tid & 31, wid = tid >> 5;
    const int wc = wid >> 2, wr = wid & 3;
    const int g = lane >> 2, q4 = lane & 3;
    const int mrow = wr * 16 + g;
    const size_t base = (size_t)blockIdx.y * Tn * Hn;

    for (int pass = 0; pass < 2; pass++) {
        const int qt = pass ? (63 - (int)blockIdx.x) : (int)blockIdx.x;
        __syncthreads();  // previous pass fully done
        if (tid < 64) { msh[tid] = -1e30f; lsh[tid] = 0.f; }

        // Q tile: raw bit copy (already tf32 + scaled)
#pragma unroll
        for (int i = 0; i < 4; i++) {
            int idx = tid + i * 256;
            int r = idx >> 4, c4 = (idx & 15) * 4;
            uint4 v = *(const uint4*)&g_q[base + (size_t)(qt * 64 + r) * 64 + c4];
            *(uint4*)&qs[r * 68 + c4] = v;
        }

        // prefetch KV tile 0 into buffer 0
#pragma unroll
        for (int i = 0; i < 4; i++) {
            int idx = tid + i * 256;
            int r = idx >> 4, cf = (idx & 15) * 4;
            size_t gofs = base + (size_t)(0 * 64 + r) * 64 + cf;
            cpa16(&ks_[r * 68 + cf], &g_k[gofs]);
            cpa16(&vs[r * 72 + cf], &g_v[gofs]);
        }
        CP_COMMIT();

        float o[4][4];
#pragma unroll
        for (int nt = 0; nt < 4; nt++)
#pragma unroll
            for (int i = 0; i < 4; i++) o[nt][i] = 0.f;

        for (int j = 0; j <= qt; j++) {
            const int bf = j & 1;
            uint32_t* kb = ks_ + bf * 4352;
            uint32_t* vb = vs + bf * 4608;
            CP_WAIT0();
            __syncthreads();
            if (j < qt) {
                const int nb = (j + 1) & 1;
                uint32_t* kn = ks_ + nb * 4352;
                uint32_t* vn = vs + nb * 4608;
#pragma unroll
                for (int i = 0; i < 4; i++) {
                    int idx = tid + i * 256;
                    int r = idx >> 4, cf = (idx & 15) * 4;
                    size_t gofs = base + (size_t)((j + 1) * 64 + r) * 64 + cf;
                    cpa16(&kn[r * 68 + cf], &g_k[gofs]);
                    cpa16(&vn[r * 72 + cf], &g_v[gofs]);
                }
                CP_COMMIT();
            }

            // S = (Q/8) K^T : warp tile 16 x 32
            float s[4][4];
#pragma unroll
            for (int nt = 0; nt < 4; nt++)
#pragma unroll
                for (int i = 0; i < 4; i++) s[nt][i] = 0.f;
#pragma unroll
            for (int ksx = 0; ksx < 8; ksx++) {
                int kk = ksx * 8 + q4;
                uint32_t a[4] = { qs[mrow * 68 + kk], qs[(mrow + 8) * 68 + kk],
                                  qs[mrow * 68 + kk + 4], qs[(mrow + 8) * 68 + kk + 4] };
#pragma unroll
                for (int nt = 0; nt < 4; nt++) {
                    int n = wc * 32 + nt * 8 + g;
                    uint32_t bb[2] = { kb[n * 68 + kk], kb[n * 68 + kk + 4] };
                    mma8(s[nt], a, bb);
                }
            }
            if (j == qt) {
#pragma unroll
                for (int nt = 0; nt < 4; nt++) {
                    int c0 = wc * 32 + nt * 8 + 2 * q4;
                    if (c0 > mrow)         s[nt][0] = -1e30f;
                    if (c0 + 1 > mrow)     s[nt][1] = -1e30f;
                    if (c0 > mrow + 8)     s[nt][2] = -1e30f;
                    if (c0 + 1 > mrow + 8) s[nt][3] = -1e30f;
                }
            }
            float mx0 = -1e30f, mx1 = -1e30f;
#pragma unroll
            for (int nt = 0; nt < 4; nt++) {
                mx0 = fmaxf(mx0, fmaxf(s[nt][0], s[nt][1]));
                mx1 = fmaxf(mx1, fmaxf(s[nt][2], s[nt][3]));
            }
            mx0 = fmaxf(mx0, __shfl_xor_sync(~0u, mx0, 1));
            mx0 = fmaxf(mx0, __shfl_xor_sync(~0u, mx0, 2));
            mx1 = fmaxf(mx1, __shfl_xor_sync(~0u, mx1, 1));
            mx1 = fmaxf(mx1, __shfl_xor_sync(~0u, mx1, 2));
            if (q4 == 0) { pmax[wc * 64 + mrow] = mx0; pmax[wc * 64 + mrow + 8] = mx1; }
            __syncthreads();

            float mold0 = msh[mrow], mold1 = msh[mrow + 8];
            float mn0 = fmaxf(mold0, fmaxf(pmax[mrow], pmax[64 + mrow]));
            float mn1 = fmaxf(mold1, fmaxf(pmax[mrow + 8], pmax[64 + mrow + 8]));
            float corr0 = __expf(mold0 - mn0), corr1 = __expf(mold1 - mn1);
            float sum0 = 0.f, sum1 = 0.f;
#pragma unroll
            for (int nt = 0; nt < 4; nt++) {
                float p0 = __expf(s[nt][0] - mn0), p1 = __expf(s[nt][1] - mn0);
                float p2 = __expf(s[nt][2] - mn1), p3 = __expf(s[nt][3] - mn1);
                sum0 += p0 + p1; sum1 += p2 + p3;
                int c = wc * 32 + nt * 8 + 2 * q4;
                *(uint2*)&ps[mrow * 68 + c]       = make_uint2(f2tf(p0), f2tf(p1));
                *(uint2*)&ps[(mrow + 8) * 68 + c] = make_uint2(f2tf(p2), f2tf(p3));
            }
            sum0 += __shfl_xor_sync(~0u, sum0, 1); sum0 += __shfl_xor_sync(~0u, sum0, 2);
            sum1 += __shfl_xor_sync(~0u, sum1, 1); sum1 += __shfl_xor_sync(~0u, sum1, 2);
            if (q4 == 0) { psum[wc * 64 + mrow] = sum0; psum[wc * 64 + mrow + 8] = sum1; }
            __syncthreads();

            if (wc == 0 && q4 == 0) {
                lsh[mrow]     = lsh[mrow] * corr0 + psum[mrow] + psum[64 + mrow];
                lsh[mrow + 8] = lsh[mrow + 8] * corr1 + psum[mrow + 8] + psum[64 + mrow + 8];
                msh[mrow] = mn0; msh[mrow + 8] = mn1;
            }
#pragma unroll
            for (int nt = 0; nt < 4; nt++) {
                o[nt][0] *= corr0; o[nt][1] *= corr0;
                o[nt][2] *= corr1; o[nt][3] *= corr1;
            }
#pragma unroll
            for (int ksx = 0; ksx < 8; ksx++) {
                int kk = ksx * 8 + q4;
                uint32_t a[4] = { ps[mrow * 68 + kk], ps[(mrow + 8) * 68 + kk],
                                  ps[mrow * 68 + kk + 4], ps[(mrow + 8) * 68 + kk + 4] };
#pragma unroll
                for (int nt = 0; nt < 4; nt++) {
                    int h = wc * 32 + nt * 8 + g;
                    uint32_t bb[2] = { vb[kk * 72 + h], vb[(kk + 4) * 72 + h] };
                    mma8(o[nt], a, bb);
                }
            }
        }
        __syncthreads();
        float li0 = 1.f / lsh[mrow], li1 = 1.f / lsh[mrow + 8];
#pragma unroll
        for (int nt = 0; nt < 4; nt++) {
            int c = wc * 32 + nt * 8 + 2 * q4;
            size_t r0 = base + (size_t)(qt * 64 + mrow) * 64 + c;
            *(float2*)&out[r0] = make_float2(o[nt][0] * li0, o[nt][1] * li0);
            *(float2*)&out[r0 + 8 * 64] = make_float2(o[nt][2] * li1, o[nt][3] * li1);
        }
    }
}

// ---------------------------------------------------------------------------
extern "C" void kernel_launch(void* const* d_in, const int* in_sizes, int n_in,
                              void* d_out, int out_size)
{
    const float* x  = (const float*)d_in[0];
    const float* Wk = (const float*)d_in[1];
    const float* Wq = (const float*)d_in[2];
    const float* Wv = (const float*)d_in[3];
    float* out = (float*)d_out;

    cudaFuncSetAttribute(proj_kernel, cudaFuncAttributeMaxDynamicSharedMemorySize, PJ_SMEM);
    cudaFuncSetAttribute(attn_kernel, cudaFuncAttributeMaxDynamicSharedMemorySize, AT_SMEM);

    proj_kernel<<<(Bn * Tn) / 64, 256, PJ_SMEM>>>(x, Wq, Wk, Wv);
    attn_kernel<<<dim3(Tn / 128, Bn), 256, AT_SMEM>>>(out);
}

// round 4
// speedup vs baseline: 4.9352x; 1.1699x over previous
#include <cuda_runtime.h>
#include <cstdint>

#define Bn 4
#define Tn 4096
#define Cn 1024
#define Hn 64

// Scratch (tf32-rounded fp32 bit patterns). g_q has 0.125*log2(e) folded via Wq.
__device__ __align__(16) float g_q[Bn * Tn * Hn];
__device__ __align__(16) float g_k[Bn * Tn * Hn];
__device__ __align__(16) float g_v[Bn * Tn * Hn];
__device__ __align__(16) uint32_t g_wt[1024 * 192];      // pre-converted W: [k][q|k|v cols]
// Split-KV partials: [e][b][qt][row][col] and [e][b][qt][row]
__device__ __align__(16) float g_po[2 * 4 * 64 * 64 * 64];
__device__ float g_pm[2 * 4 * 64 * 64];
__device__ float g_pl[2 * 4 * 64 * 64];

__device__ __forceinline__ uint32_t f2tf(float f) {
    uint32_t r;
    asm("cvt.rna.tf32.f32 %0, %1;" : "=r"(r) : "f"(f));
    return r;
}

__device__ __forceinline__ void mma8(float* c, const uint32_t* a, const uint32_t* b) {
    asm volatile(
        "mma.sync.aligned.m16n8k8.row.col.f32.tf32.tf32.f32 "
        "{%0,%1,%2,%3}, {%4,%5,%6,%7}, {%8,%9}, {%0,%1,%2,%3};"
        : "+f"(c[0]), "+f"(c[1]), "+f"(c[2]), "+f"(c[3])
        : "r"(a[0]), "r"(a[1]), "r"(a[2]), "r"(a[3]), "r"(b[0]), "r"(b[1]));
}

__device__ __forceinline__ void cpa16(void* dst, const void* src) {
    uint32_t d = (uint32_t)__cvta_generic_to_shared(dst);
    asm volatile("cp.async.cg.shared.global [%0], [%1], 16;" :: "r"(d), "l"(src));
}
#define CP_COMMIT() asm volatile("cp.async.commit_group;")
#define CP_WAIT0()  asm volatile("cp.async.wait_group 0;")

// ---------------------------------------------------------------------------
// W pre-convert: g_wt[k][c] (c<64: Wq*scale, <128: Wk, <192: Wv), tf32.
// ---------------------------------------------------------------------------
__global__ void cvtw_kernel(const float* __restrict__ Wq,
                            const float* __restrict__ Wk,
                            const float* __restrict__ Wv)
{
    const float QS = 0.125f * 1.44269504088896f;  // H^-0.5 * log2(e)
    int i = blockIdx.x * 256 + threadIdx.x;
    if (i >= 1024 * 192) return;
    int k = i / 192, c = i % 192;
    float v;
    if (c < 64)       v = Wq[k * 64 + c] * QS;
    else if (c < 128) v = Wk[k * 64 + (c - 64)];
    else              v = Wv[k * 64 + (c - 128)];
    g_wt[i] = f2tf(v);
}

// ---------------------------------------------------------------------------
// Projection: y = x @ {Wq*s, Wk, Wv}. M=16384, K=1024, N=192.
// Double-buffered: W via cp.async (pre-converted), x register-staged.
// ---------------------------------------------------------------------------
#define PJ_SMEM ((2 * 2304 + 2 * 6400) * 4)

__global__ __launch_bounds__(256, 2) void proj_kernel(const float* __restrict__ x)
{
    extern __shared__ uint32_t sm[];
    uint32_t* xs = sm;             // 2 x [64][36]
    uint32_t* ws = sm + 2 * 2304;  // 2 x [32][200]

    const int tid = threadIdx.x;
    const int lane = tid & 31, wid = tid >> 5;
    const int m0 = blockIdx.x * 64;
    const int g = lane >> 2, q4 = lane & 3;

    const int xr_r = tid >> 3, xr_c = (tid & 7) * 4;          // x-load coords (2 chunks)
    const int w_kk0 = tid / 48, w_c0 = (tid % 48) * 4;        // W chunk 0 base

    float acc[4][3][4];
#pragma unroll
    for (int mt = 0; mt < 4; mt++)
#pragma unroll
        for (int nt = 0; nt < 3; nt++)
#pragma unroll
            for (int i = 0; i < 4; i++) acc[mt][nt][i] = 0.f;

    // prologue: W0 via cp.async, x0 via LDG+cvt+STS
#pragma unroll
    for (int i = 0; i < 6; i++) {
        int idx = tid + i * 256;
        int kk = idx / 48, c = idx % 48;
        cpa16(&ws[kk * 200 + c * 4], &g_wt[(size_t)kk * 192 + c * 4]);
    }
    CP_COMMIT();
    float4 xr[2];
#pragma unroll
    for (int i = 0; i < 2; i++) {
        int idx = tid + i * 256;
        int r = idx >> 3, c4 = (idx & 7) * 4;
        xr[i] = *(const float4*)&x[(size_t)(m0 + r) * Cn + c4];
    }
#pragma unroll
    for (int i = 0; i < 2; i++) {
        int idx = tid + i * 256;
        int r = idx >> 3, c4 = (idx & 7) * 4;
        uint32_t* d = &xs[r * 36 + c4];
        d[0] = f2tf(xr[i].x); d[1] = f2tf(xr[i].y); d[2] = f2tf(xr[i].z); d[3] = f2tf(xr[i].w);
    }

    for (int j = 0; j < 32; j++) {
        uint32_t* xsj = xs + (j & 1) * 2304;
        uint32_t* wsj = ws + (j & 1) * 6400;
        CP_WAIT0();
        __syncthreads();
        if (j < 31) {
            int k0n = (j + 1) * 32;
            uint32_t* wn = ws + ((j + 1) & 1) * 6400;
#pragma unroll
            for (int i = 0; i < 6; i++) {
                int idx = tid + i * 256;
                int kk = idx / 48, c = idx % 48;
                cpa16(&wn[kk * 200 + c * 4], &g_wt[(size_t)(k0n + kk) * 192 + c * 4]);
            }
            CP_COMMIT();
#pragma unroll
            for (int i = 0; i < 2; i++) {
                int idx = tid + i * 256;
                int r = idx >> 3, c4 = (idx & 7) * 4;
                xr[i] = *(const float4*)&x[(size_t)(m0 + r) * Cn + k0n + c4];
            }
        }

#pragma unroll
        for (int ksx = 0; ksx < 4; ksx++) {
            int kk = ksx * 8 + q4;
            uint32_t bfr[3][2];
#pragma unroll
            for (int nt = 0; nt < 3; nt++) {
                int n = wid * 24 + nt * 8 + g;
                bfr[nt][0] = wsj[kk * 200 + n];
                bfr[nt][1] = wsj[(kk + 4) * 200 + n];
            }
#pragma unroll
            for (int mt = 0; mt < 4; mt++) {
                int r = mt * 16 + g;
                uint32_t a[4] = { xsj[r * 36 + kk], xsj[(r + 8) * 36 + kk],
                                  xsj[r * 36 + kk + 4], xsj[(r + 8) * 36 + kk + 4] };
#pragma unroll
                for (int nt = 0; nt < 3; nt++) mma8(acc[mt][nt], a, bfr[nt]);
            }
        }

        if (j < 31) {
            uint32_t* xn = xs + ((j + 1) & 1) * 2304;
#pragma unroll
            for (int i = 0; i < 2; i++) {
                int idx = tid + i * 256;
                int r = idx >> 3, c4 = (idx & 7) * 4;
                uint32_t* d = &xn[r * 36 + c4];
                d[0] = f2tf(xr[i].x); d[1] = f2tf(xr[i].y); d[2] = f2tf(xr[i].z); d[3] = f2tf(xr[i].w);
            }
        }
    }

#pragma unroll
    for (int mt = 0; mt < 4; mt++)
#pragma unroll
        for (int nt = 0; nt < 3; nt++) {
            int col = wid * 24 + nt * 8;
            float* dst = (col < 64) ? g_q : (col < 128) ? g_k : g_v;
            int h = (col & 63) + 2 * q4;
            size_t r = (size_t)(m0 + mt * 16 + g) * 64 + h;
            *(uint2*)&dst[r] = make_uint2(f2tf(acc[mt][nt][0]), f2tf(acc[mt][nt][1]));
            *(uint2*)&dst[r + 8 * 64] = make_uint2(f2tf(acc[mt][nt][2]), f2tf(acc[mt][nt][3]));
        }
}

// ---------------------------------------------------------------------------
// Causal flash attention, parity split-KV, split-accumulator warps.
// grid (64, 4): CTA (p = bx>>1, e = bx&1) does q-tiles p and 63-p over
// KV tiles j ≡ e (mod 2). 8 warps = 4 row-groups x 2 key-halves, each with
// independent online softmax; merged once at epilogue; parities merged in
// a separate kernel. One __syncthreads per step.
// ---------------------------------------------------------------------------
#define AT_SMEM ((2 * 4352 + 2 * 4608 + 4352 + 8 * 576) * 4)

__global__ __launch_bounds__(256, 2) void attn_kernel()
{
    extern __shared__ uint32_t sm[];
    uint32_t* ks_ = sm;               // 2 x [64][68]
    uint32_t* vs  = sm + 8704;        // 2 x [64][72]
    uint32_t* qs  = sm + 17920;       // [64][68]
    uint32_t* ps  = sm + 22272;       // 8 x [16][36] per-warp P scratch
    float* Om  = (float*)vs;          // epilogue reuse: [64][64]
    float* m1a = (float*)ks_;         // epilogue reuse: [64]
    float* l1a = m1a + 64;

    const int tid = threadIdx.x, lane = tid & 31, wid = tid >> 5;
    const int wc = wid >> 2, wr = wid & 3;
    const int g = lane >> 2, q4 = lane & 3;
    const int mrow = wr * 16 + g;
    const int e = blockIdx.x & 1, p = blockIdx.x >> 1;
    const int by = blockIdx.y;
    const size_t base = (size_t)by * Tn * Hn;
    uint32_t* ps_w = ps + wid * 576;

    for (int pass = 0; pass < 2; pass++) {
        const int qt = pass ? 63 - p : p;

        // load Q tile (raw tf32 bits, scale folded in Wq)
#pragma unroll
        for (int i = 0; i < 4; i++) {
            int idx = tid + i * 256;
            int r = idx >> 4, c4 = (idx & 15) * 4;
            uint4 v = *(const uint4*)&g_q[base + (size_t)(qt * 64 + r) * 64 + c4];
            *(uint4*)&qs[r * 68 + c4] = v;
        }
        // prefetch first KV tile
        if (e <= qt) {
#pragma unroll
            for (int i = 0; i < 4; i++) {
                int idx = tid + i * 256;
                int r = idx >> 4, cf = (idx & 15) * 4;
                size_t go = base + (size_t)(e * 64 + r) * 64 + cf;
                cpa16(&ks_[r * 68 + cf], &g_k[go]);
                cpa16(&vs[r * 72 + cf], &g_v[go]);
            }
            CP_COMMIT();
        }

        float o[8][4];
#pragma unroll
        for (int nt = 0; nt < 8; nt++)
#pragma unroll
            for (int i = 0; i < 4; i++) o[nt][i] = 0.f;
        float mA = -1e30f, mB = -1e30f, lA = 0.f, lB = 0.f;

        int t = 0;
        for (int j = e; j <= qt; j += 2, t++) {
            uint32_t* kb = ks_ + (t & 1) * 4352;
            uint32_t* vb = vs + (t & 1) * 4608;
            CP_WAIT0();
            __syncthreads();
            if (j + 2 <= qt) {
                uint32_t* kn = ks_ + ((t + 1) & 1) * 4352;
                uint32_t* vn = vs + ((t + 1) & 1) * 4608;
#pragma unroll
                for (int i = 0; i < 4; i++) {
                    int idx = tid + i * 256;
                    int r = idx >> 4, cf = (idx & 15) * 4;
                    size_t go = base + (size_t)((j + 2) * 64 + r) * 64 + cf;
                    cpa16(&kn[r * 68 + cf], &g_k[go]);
                    cpa16(&vn[r * 72 + cf], &g_v[go]);
                }
                CP_COMMIT();
            }

            // S = Q K^T over this warp's 32-key half (log2 domain)
            float s[4][4];
#pragma unroll
            for (int nt = 0; nt < 4; nt++)
#pragma unroll
                for (int i = 0; i < 4; i++) s[nt][i] = 0.f;
#pragma unroll
            for (int k8 = 0; k8 < 8; k8++) {
                int kk = k8 * 8 + q4;
                uint32_t a[4] = { qs[mrow * 68 + kk], qs[(mrow + 8) * 68 + kk],
                                  qs[mrow * 68 + kk + 4], qs[(mrow + 8) * 68 + kk + 4] };
#pragma unroll
                for (int nt = 0; nt < 4; nt++) {
                    int n = wc * 32 + nt * 8 + g;
                    uint32_t b2[2] = { kb[n * 68 + kk], kb[n * 68 + kk + 4] };
                    mma8(s[nt], a, b2);
                }
            }
            if (j == qt) {
#pragma unroll
                for (int nt = 0; nt < 4; nt++) {
                    int c0 = wc * 32 + nt * 8 + 2 * q4;
                    if (c0 > mrow)         s[nt][0] = -1e30f;
                    if (c0 + 1 > mrow)     s[nt][1] = -1e30f;
                    if (c0 > mrow + 8)     s[nt][2] = -1e30f;
                    if (c0 + 1 > mrow + 8) s[nt][3] = -1e30f;
                }
            }

            // per-warp online softmax (no CTA-level exchange)
            float mx0 = -1e30f, mx1 = -1e30f;
#pragma unroll
            for (int nt = 0; nt < 4; nt++) {
                mx0 = fmaxf(mx0, fmaxf(s[nt][0], s[nt][1]));
                mx1 = fmaxf(mx1, fmaxf(s[nt][2], s[nt][3]));
            }
            mx0 = fmaxf(mx0, __shfl_xor_sync(~0u, mx0, 1));
            mx0 = fmaxf(mx0, __shfl_xor_sync(~0u, mx0, 2));
            mx1 = fmaxf(mx1, __shfl_xor_sync(~0u, mx1, 1));
            mx1 = fmaxf(mx1, __shfl_xor_sync(~0u, mx1, 2));
            float mn0 = fmaxf(mA, mx0), mn1 = fmaxf(mB, mx1);
            float corr0 = exp2f(mA - mn0), corr1 = exp2f(mB - mn1);
            float sum0 = 0.f, sum1 = 0.f;
#pragma unroll
            for (int nt = 0; nt < 4; nt++) {
                float p0 = exp2f(s[nt][0] - mn0), p1 = exp2f(s[nt][1] - mn0);
                float p2 = exp2f(s[nt][2] - mn1), p3 = exp2f(s[nt][3] - mn1);
                sum0 += p0 + p1; sum1 += p2 + p3;
                int cb = nt * 8 + 2 * q4;
                *(uint2*)&ps_w[g * 36 + cb]       = make_uint2(f2tf(p0), f2tf(p1));
                *(uint2*)&ps_w[(g + 8) * 36 + cb] = make_uint2(f2tf(p2), f2tf(p3));
            }
            sum0 += __shfl_xor_sync(~0u, sum0, 1); sum0 += __shfl_xor_sync(~0u, sum0, 2);
            sum1 += __shfl_xor_sync(~0u, sum1, 1); sum1 += __shfl_xor_sync(~0u, sum1, 2);
            lA = lA * corr0 + sum0; lB = lB * corr1 + sum1;
            mA = mn0; mB = mn1;
            __syncwarp();

#pragma unroll
            for (int nt = 0; nt < 8; nt++) {
                o[nt][0] *= corr0; o[nt][1] *= corr0;
                o[nt][2] *= corr1; o[nt][3] *= corr1;
            }
            // O += P V  (P private; V rows = this warp's key half; all 64 h cols)
#pragma unroll
            for (int kg = 0; kg < 4; kg++) {
                int kk = kg * 8 + q4;
                uint32_t a[4] = { ps_w[g * 36 + kk], ps_w[(g + 8) * 36 + kk],
                                  ps_w[g * 36 + kk + 4], ps_w[(g + 8) * 36 + kk + 4] };
#pragma unroll
                for (int nt = 0; nt < 8; nt++) {
                    int h = nt * 8 + g;
                    uint32_t b2[2] = { vb[(wc * 32 + kk) * 72 + h],
                                       vb[(wc * 32 + kk + 4) * 72 + h] };
                    mma8(o[nt], a, b2);
                }
            }
        }

        // epilogue: merge wc halves, write unnormalized partial
        __syncthreads();
        if (wc == 1) {
            if (q4 == 0) {
                m1a[mrow] = mA; m1a[mrow + 8] = mB;
                l1a[mrow] = lA; l1a[mrow + 8] = lB;
            }
#pragma unroll
            for (int nt = 0; nt < 8; nt++) {
                int cb = nt * 8 + 2 * q4;
                *(float2*)&Om[mrow * 64 + cb]       = make_float2(o[nt][0], o[nt][1]);
                *(float2*)&Om[(mrow + 8) * 64 + cb] = make_float2(o[nt][2], o[nt][3]);
            }
        }
        __syncthreads();
        if (wc == 0) {
            float m1w = m1a[mrow], l1w = l1a[mrow];
            float m1x = m1a[mrow + 8], l1x = l1a[mrow + 8];
            float mf0 = fmaxf(mA, m1w), mf1 = fmaxf(mB, m1x);
            float cA0 = exp2f(mA - mf0), cB0 = exp2f(m1w - mf0);
            float cA1 = exp2f(mB - mf1), cB1 = exp2f(m1x - mf1);
            float lf0 = lA * cA0 + l1w * cB0;
            float lf1 = lB * cA1 + l1x * cB1;
            int mlb = ((e * 4 + by) * 64 + qt) * 64;
            if (q4 == 0) {
                g_pm[mlb + mrow] = mf0; g_pm[mlb + mrow + 8] = mf1;
                g_pl[mlb + mrow] = lf0; g_pl[mlb + mrow + 8] = lf1;
            }
            size_t pob = ((size_t)(e * 4 + by) * 64 + qt) * 4096;
#pragma unroll
            for (int nt = 0; nt < 8; nt++) {
                int cb = nt * 8 + 2 * q4;
                float2 v0 = *(float2*)&Om[mrow * 64 + cb];
                *(float2*)&g_po[pob + mrow * 64 + cb] =
                    make_float2(o[nt][0] * cA0 + v0.x * cB0, o[nt][1] * cA0 + v0.y * cB0);
                float2 v1 = *(float2*)&Om[(mrow + 8) * 64 + cb];
                *(float2*)&g_po[pob + (mrow + 8) * 64 + cb] =
                    make_float2(o[nt][2] * cA1 + v1.x * cB1, o[nt][3] * cA1 + v1.y * cB1);
            }
        }
        __syncthreads();
    }
}

// ---------------------------------------------------------------------------
// Merge the two parity partials -> final normalized output.
// ---------------------------------------------------------------------------
__global__ void merge_kernel(float* __restrict__ out)
{
    int idx = blockIdx.x * 256 + threadIdx.x;       // < 4*64*64*32
    int c2  = idx & 31;
    int row = (idx >> 5) & 63;
    int qt  = (idx >> 11) & 63;
    int b   = idx >> 17;
    int mlb = (b * 64 + qt) * 64 + row;
    float m0 = g_pm[mlb],         l0 = g_pl[mlb];
    float m1 = g_pm[mlb + 16384], l1 = g_pl[mlb + 16384];
    float mf = fmaxf(m0, m1);
    float c0 = exp2f(m0 - mf), c1 = exp2f(m1 - mf);
    float inv = 1.f / (l0 * c0 + l1 * c1);
    size_t p0 = ((size_t)(b * 64) + qt) * 4096 + row * 64 + 2 * c2;
    float2 a = *(float2*)&g_po[p0];
    float2 bb = *(float2*)&g_po[p0 + 1048576];
    float2 r = make_float2((a.x * c0 + bb.x * c1) * inv, (a.y * c0 + bb.y * c1) * inv);
    *(float2*)&out[((size_t)b * 4096 + qt * 64 + row) * 64 + 2 * c2] = r;
}

// ---------------------------------------------------------------------------
extern "C" void kernel_launch(void* const* d_in, const int* in_sizes, int n_in,
                              void* d_out, int out_size)
{
    const float* x  = (const float*)d_in[0];
    const float* Wk = (const float*)d_in[1];
    const float* Wq = (const float*)d_in[2];
    const float* Wv = (const float*)d_in[3];
    float* out = (float*)d_out;

    cudaFuncSetAttribute(proj_kernel, cudaFuncAttributeMaxDynamicSharedMemorySize, PJ_SMEM);
    cudaFuncSetAttribute(attn_kernel, cudaFuncAttributeMaxDynamicSharedMemorySize, AT_SMEM);

    cvtw_kernel<<<768, 256>>>(Wq, Wk, Wv);
    proj_kernel<<<(Bn * Tn) / 64, 256, PJ_SMEM>>>(x);
    attn_kernel<<<dim3(64, Bn), 256, AT_SMEM>>>();
    merge_kernel<<<2048, 256>>>(out);
}

// round 5
// speedup vs baseline: 7.3890x; 1.4972x over previous
#include <cuda_runtime.h>
#include <cuda_fp16.h>
#include <cstdint>

#define Bn 4
#define Tn 4096
#define Cn 1024
#define Hn 64

// fp16 scratch. g_q has 0.125*log2(e) folded (via Wq). g_vt is V TRANSPOSED [b][h][t].
__device__ __align__(16) __half g_q[Bn * Tn * Hn];
__device__ __align__(16) __half g_k[Bn * Tn * Hn];
__device__ __align__(16) __half g_vt[Bn * Hn * Tn];
__device__ __align__(16) __half g_wt[192 * 1024];   // W transposed fp16: [col][k]
// Split-KV partials (fp32): [e][b][qt][row][col] / [e][b][qt][row]
__device__ __align__(16) float g_po[2 * 4 * 64 * 64 * 64];
__device__ float g_pm[2 * 4 * 64 * 64];
__device__ float g_pl[2 * 4 * 64 * 64];

__device__ __forceinline__ void mmah(float* c, const uint32_t* a, const uint32_t* b) {
    asm volatile(
        "mma.sync.aligned.m16n8k16.row.col.f32.f16.f16.f32 "
        "{%0,%1,%2,%3}, {%4,%5,%6,%7}, {%8,%9}, {%0,%1,%2,%3};"
        : "+f"(c[0]), "+f"(c[1]), "+f"(c[2]), "+f"(c[3])
        : "r"(a[0]), "r"(a[1]), "r"(a[2]), "r"(a[3]), "r"(b[0]), "r"(b[1]));
}

__device__ __forceinline__ void cpa16(void* dst, const void* src) {
    uint32_t d = (uint32_t)__cvta_generic_to_shared(dst);
    asm volatile("cp.async.cg.shared.global [%0], [%1], 16;" :: "r"(d), "l"(src));
}
#define CP_COMMIT() asm volatile("cp.async.commit_group;")
#define CP_WAIT0()  asm volatile("cp.async.wait_group 0;")

__device__ __forceinline__ uint32_t h2u(__half2 h) { return *reinterpret_cast<uint32_t*>(&h); }

// ---------------------------------------------------------------------------
// W pre-convert, transposed: g_wt[c][k]; c<64 -> Wq*QS, <128 -> Wk, <192 -> Wv.
// ---------------------------------------------------------------------------
__global__ void cvtw_kernel(const float* __restrict__ Wq,
                            const float* __restrict__ Wk,
                            const float* __restrict__ Wv)
{
    const float QS = 0.125f * 1.44269504088896f;
    int i = blockIdx.x * 256 + threadIdx.x;        // i = c*1024 + k
    if (i >= 192 * 1024) return;
    int c = i >> 10, k = i & 1023;
    float v;
    if (c < 64)       v = Wq[k * 64 + c] * QS;
    else if (c < 128) v = Wk[k * 64 + (c - 64)];
    else              v = Wv[k * 64 + (c - 128)];
    g_wt[i] = __float2half_rn(v);
}

// ---------------------------------------------------------------------------
// Projection: y = x @ {Wq*s, Wk, Wv}, fp16 m16n8k16. M=16384, K=1024, N=192.
// Block = 64 rows, 8 warps, warp owns 24 cols. K-chunk 32, double-buffered.
// ---------------------------------------------------------------------------
#define PJ_SMEM ((2 * 2560 + 2 * 7680) * 2)

__global__ __launch_bounds__(256, 2) void proj_kernel(const float* __restrict__ x)
{
    extern __shared__ __half smh[];
    __half* xs = smh;               // 2 x [64][40]  (x rows, k cols)
    __half* ws = smh + 2 * 2560;    // 2 x [192][40] (W cols as rows, k cols)

    const int tid = threadIdx.x;
    const int lane = tid & 31, wid = tid >> 5;
    const int m0 = blockIdx.x * 64;
    const int g = lane >> 2, q4 = lane & 3;

    float acc[4][3][4];
#pragma unroll
    for (int mt = 0; mt < 4; mt++)
#pragma unroll
        for (int nt = 0; nt < 3; nt++)
#pragma unroll
            for (int i = 0; i < 4; i++) acc[mt][nt][i] = 0.f;

    // prologue: W chunk0 via cp.async (rows n=192, 32 halves = 4x16B)
#pragma unroll
    for (int i = 0; i < 3; i++) {
        int idx = tid + i * 256;
        int n = idx >> 2, cf = (idx & 3) * 8;
        cpa16(&ws[n * 40 + cf], &g_wt[n * 1024 + cf]);
    }
    CP_COMMIT();
    float4 xr[2];
#pragma unroll
    for (int i = 0; i < 2; i++) {
        int idx = tid + i * 256;
        int r = idx >> 3, c4 = (idx & 7) * 4;
        xr[i] = *(const float4*)&x[(size_t)(m0 + r) * Cn + c4];
    }
#pragma unroll
    for (int i = 0; i < 2; i++) {
        int idx = tid + i * 256;
        int r = idx >> 3, c4 = (idx & 7) * 4;
        *(__half2*)&xs[r * 40 + c4]     = __floats2half2_rn(xr[i].x, xr[i].y);
        *(__half2*)&xs[r * 40 + c4 + 2] = __floats2half2_rn(xr[i].z, xr[i].w);
    }

    for (int j = 0; j < 32; j++) {
        __half* xsj = xs + (j & 1) * 2560;
        __half* wsj = ws + (j & 1) * 7680;
        CP_WAIT0();
        __syncthreads();
        if (j < 31) {
            int k0n = (j + 1) * 32;
            __half* wn = ws + ((j + 1) & 1) * 7680;
#pragma unroll
            for (int i = 0; i < 3; i++) {
                int idx = tid + i * 256;
                int n = idx >> 2, cf = (idx & 3) * 8;
                cpa16(&wn[n * 40 + cf], &g_wt[n * 1024 + k0n + cf]);
            }
            CP_COMMIT();
#pragma unroll
            for (int i = 0; i < 2; i++) {
                int idx = tid + i * 256;
                int r = idx >> 3, c4 = (idx & 7) * 4;
                xr[i] = *(const float4*)&x[(size_t)(m0 + r) * Cn + k0n + c4];
            }
        }

#pragma unroll
        for (int k16 = 0; k16 < 2; k16++) {
            int kk = k16 * 16 + 2 * q4;
            uint32_t bfr[3][2];
#pragma unroll
            for (int nt = 0; nt < 3; nt++) {
                int n = wid * 24 + nt * 8 + g;
                bfr[nt][0] = *(const uint32_t*)&wsj[n * 40 + kk];
                bfr[nt][1] = *(const uint32_t*)&wsj[n * 40 + kk + 8];
            }
#pragma unroll
            for (int mt = 0; mt < 4; mt++) {
                int r = mt * 16 + g;
                uint32_t a[4] = { *(const uint32_t*)&xsj[r * 40 + kk],
                                  *(const uint32_t*)&xsj[(r + 8) * 40 + kk],
                                  *(const uint32_t*)&xsj[r * 40 + kk + 8],
                                  *(const uint32_t*)&xsj[(r + 8) * 40 + kk + 8] };
#pragma unroll
                for (int nt = 0; nt < 3; nt++) mmah(acc[mt][nt], a, bfr[nt]);
            }
        }

        if (j < 31) {
            __half* xn = xs + ((j + 1) & 1) * 2560;
#pragma unroll
            for (int i = 0; i < 2; i++) {
                int idx = tid + i * 256;
                int r = idx >> 3, c4 = (idx & 7) * 4;
                *(__half2*)&xn[r * 40 + c4]     = __floats2half2_rn(xr[i].x, xr[i].y);
                *(__half2*)&xn[r * 40 + c4 + 2] = __floats2half2_rn(xr[i].z, xr[i].w);
            }
        }
    }

    const int bb = m0 >> 12, t0 = m0 & 4095;
#pragma unroll
    for (int mt = 0; mt < 4; mt++)
#pragma unroll
        for (int nt = 0; nt < 3; nt++) {
            int col = wid * 24 + nt * 8;
            if (col < 128) {
                __half* dst = (col < 64) ? g_q : g_k;
                int h = (col & 63) + 2 * q4;
                size_t r = (size_t)(m0 + mt * 16 + g) * 64 + h;
                *(__half2*)&dst[r] = __floats2half2_rn(acc[mt][nt][0], acc[mt][nt][1]);
                *(__half2*)&dst[r + 8 * 64] = __floats2half2_rn(acc[mt][nt][2], acc[mt][nt][3]);
            } else {
                int h = (col - 128) + 2 * q4;
                int tr = t0 + mt * 16 + g;
                __half* vp = &g_vt[((size_t)bb * 64 + h) * 4096 + tr];
                vp[0]        = __float2half_rn(acc[mt][nt][0]);
                vp[4096]     = __float2half_rn(acc[mt][nt][1]);
                vp[8]        = __float2half_rn(acc[mt][nt][2]);
                vp[4096 + 8] = __float2half_rn(acc[mt][nt][3]);
            }
        }
}

// ---------------------------------------------------------------------------
// Causal flash attention, fp16 m16n8k16, parity split-KV, per-warp softmax.
// grid (64,4): CTA (p=bx>>1, e=bx&1), q-tiles p and 63-p, KV tiles j≡e (mod 2).
// 8 warps = 4 row-groups x 2 key-halves. One __syncthreads per step.
// ---------------------------------------------------------------------------
#define AT_SMEM ((5 * 4608 + 8 * 640) * 2)

__global__ __launch_bounds__(256, 2) void attn_kernel()
{
    extern __shared__ __half smh[];
    __half* ks = smh;                 // 2 x [64 key][72]  (K)
    __half* vt = smh + 2 * 4608;      // 2 x [64 h][72]    (V transposed: [h][key])
    __half* qs = smh + 4 * 4608;      // [64 row][72]
    __half* ps = smh + 5 * 4608;      // 8 x [16][40] per-warp P
    float* Om  = (float*)vt;          // epilogue reuse [64][64]
    float* m1a = (float*)ks;          // epilogue reuse [64]
    float* l1a = m1a + 64;

    const int tid = threadIdx.x, lane = tid & 31, wid = tid >> 5;
    const int wc = wid >> 2, wr = wid & 3;
    const int g = lane >> 2, q4 = lane & 3;
    const int mrow = wr * 16 + g;
    const int e = blockIdx.x & 1, p = blockIdx.x >> 1;
    const int by = blockIdx.y;
    const size_t base = (size_t)by * Tn * Hn;
    __half* ps_w = ps + wid * 640;

    for (int pass = 0; pass < 2; pass++) {
        const int qt = pass ? 63 - p : p;

        // Q tile via cp.async (64 rows x 128B)
#pragma unroll
        for (int i = 0; i < 2; i++) {
            int idx = tid + i * 256;
            int r = idx >> 3, cf = (idx & 7) * 8;
            cpa16(&qs[r * 72 + cf], &g_q[base + (size_t)(qt * 64 + r) * 64 + cf]);
        }
        if (e <= qt) {
#pragma unroll
            for (int i = 0; i < 2; i++) {
                int idx = tid + i * 256;
                int r = idx >> 3, cf = (idx & 7) * 8;
                cpa16(&ks[r * 72 + cf], &g_k[base + (size_t)(e * 64 + r) * 64 + cf]);
                cpa16(&vt[r * 72 + cf], &g_vt[((size_t)by * 64 + r) * 4096 + e * 64 + cf]);
            }
        }
        CP_COMMIT();

        float o[8][4];
#pragma unroll
        for (int nt = 0; nt < 8; nt++)
#pragma unroll
            for (int i = 0; i < 4; i++) o[nt][i] = 0.f;
        float mA = -1e30f, mB = -1e30f, lA = 0.f, lB = 0.f;

        int t = 0;
        for (int j = e; j <= qt; j += 2, t++) {
            __half* kb = ks + (t & 1) * 4608;
            __half* vb = vt + (t & 1) * 4608;
            CP_WAIT0();
            __syncthreads();
            if (j + 2 <= qt) {
                __half* kn = ks + ((t + 1) & 1) * 4608;
                __half* vn = vt + ((t + 1) & 1) * 4608;
#pragma unroll
                for (int i = 0; i < 2; i++) {
                    int idx = tid + i * 256;
                    int r = idx >> 3, cf = (idx & 7) * 8;
                    cpa16(&kn[r * 72 + cf], &g_k[base + (size_t)((j + 2) * 64 + r) * 64 + cf]);
                    cpa16(&vn[r * 72 + cf], &g_vt[((size_t)by * 64 + r) * 4096 + (j + 2) * 64 + cf]);
                }
                CP_COMMIT();
            }

            // S = Q K^T over this warp's 32-key half
            float s[4][4];
#pragma unroll
            for (int nt = 0; nt < 4; nt++)
#pragma unroll
                for (int i = 0; i < 4; i++) s[nt][i] = 0.f;
#pragma unroll
            for (int k16 = 0; k16 < 4; k16++) {
                int kk = k16 * 16 + 2 * q4;
                uint32_t a[4] = { *(const uint32_t*)&qs[mrow * 72 + kk],
                                  *(const uint32_t*)&qs[(mrow + 8) * 72 + kk],
                                  *(const uint32_t*)&qs[mrow * 72 + kk + 8],
                                  *(const uint32_t*)&qs[(mrow + 8) * 72 + kk + 8] };
#pragma unroll
                for (int nt = 0; nt < 4; nt++) {
                    int n = wc * 32 + nt * 8 + g;
                    uint32_t b2[2] = { *(const uint32_t*)&kb[n * 72 + kk],
                                       *(const uint32_t*)&kb[n * 72 + kk + 8] };
                    mmah(s[nt], a, b2);
                }
            }
            if (j == qt) {
#pragma unroll
                for (int nt = 0; nt < 4; nt++) {
                    int c0 = wc * 32 + nt * 8 + 2 * q4;
                    if (c0 > mrow)         s[nt][0] = -1e30f;
                    if (c0 + 1 > mrow)     s[nt][1] = -1e30f;
                    if (c0 > mrow + 8)     s[nt][2] = -1e30f;
                    if (c0 + 1 > mrow + 8) s[nt][3] = -1e30f;
                }
            }

            // per-warp online softmax (log2 domain)
            float mx0 = -1e30f, mx1 = -1e30f;
#pragma unroll
            for (int nt = 0; nt < 4; nt++) {
                mx0 = fmaxf(mx0, fmaxf(s[nt][0], s[nt][1]));
                mx1 = fmaxf(mx1, fmaxf(s[nt][2], s[nt][3]));
            }
            mx0 = fmaxf(mx0, __shfl_xor_sync(~0u, mx0, 1));
            mx0 = fmaxf(mx0, __shfl_xor_sync(~0u, mx0, 2));
            mx1 = fmaxf(mx1, __shfl_xor_sync(~0u, mx1, 1));
            mx1 = fmaxf(mx1, __shfl_xor_sync(~0u, mx1, 2));
            float mn0 = fmaxf(mA, mx0), mn1 = fmaxf(mB, mx1);
            float corr0 = exp2f(mA - mn0), corr1 = exp2f(mB - mn1);
            float sum0 = 0.f, sum1 = 0.f;
#pragma unroll
            for (int nt = 0; nt < 4; nt++) {
                float p0 = exp2f(s[nt][0] - mn0), p1 = exp2f(s[nt][1] - mn0);
                float p2 = exp2f(s[nt][2] - mn1), p3 = exp2f(s[nt][3] - mn1);
                sum0 += p0 + p1; sum1 += p2 + p3;
                int cb = nt * 8 + 2 * q4;
                *(__half2*)&ps_w[g * 40 + cb]       = __floats2half2_rn(p0, p1);
                *(__half2*)&ps_w[(g + 8) * 40 + cb] = __floats2half2_rn(p2, p3);
            }
            sum0 += __shfl_xor_sync(~0u, sum0, 1); sum0 += __shfl_xor_sync(~0u, sum0, 2);
            sum1 += __shfl_xor_sync(~0u, sum1, 1); sum1 += __shfl_xor_sync(~0u, sum1, 2);
            lA = lA * corr0 + sum0; lB = lB * corr1 + sum1;
            mA = mn0; mB = mn1;
            __syncwarp();

#pragma unroll
            for (int nt = 0; nt < 8; nt++) {
                o[nt][0] *= corr0; o[nt][1] *= corr0;
                o[nt][2] *= corr1; o[nt][3] *= corr1;
            }
            // O += P V   (keys: this warp's 32; h: all 64)
#pragma unroll
            for (int kg = 0; kg < 2; kg++) {
                int kk = kg * 16 + 2 * q4;
                uint32_t a[4] = { *(const uint32_t*)&ps_w[g * 40 + kk],
                                  *(const uint32_t*)&ps_w[(g + 8) * 40 + kk],
                                  *(const uint32_t*)&ps_w[g * 40 + kk + 8],
                                  *(const uint32_t*)&ps_w[(g + 8) * 40 + kk + 8] };
#pragma unroll
                for (int nt = 0; nt < 8; nt++) {
                    int h = nt * 8 + g;
                    uint32_t b2[2] = { *(const uint32_t*)&vb[h * 72 + wc * 32 + kk],
                                       *(const uint32_t*)&vb[h * 72 + wc * 32 + kk + 8] };
                    mmah(o[nt], a, b2);
                }
            }
        }

        // epilogue: merge wc halves, write unnormalized parity partial
        __syncthreads();
        if (wc == 1) {
            if (q4 == 0) {
                m1a[mrow] = mA; m1a[mrow + 8] = mB;
                l1a[mrow] = lA; l1a[mrow + 8] = lB;
            }
#pragma unroll
            for (int nt = 0; nt < 8; nt++) {
                int cb = nt * 8 + 2 * q4;
                *(float2*)&Om[mrow * 64 + cb]       = make_float2(o[nt][0], o[nt][1]);
                *(float2*)&Om[(mrow + 8) * 64 + cb] = make_float2(o[nt][2], o[nt][3]);
            }
        }
        __syncthreads();
        if (wc == 0) {
            float m1w = m1a[mrow], l1w = l1a[mrow];
            float m1x = m1a[mrow + 8], l1x = l1a[mrow + 8];
            float mf0 = fmaxf(mA, m1w), mf1 = fmaxf(mB, m1x);
            float cA0 = exp2f(mA - mf0), cB0 = exp2f(m1w - mf0);
            float cA1 = exp2f(mB - mf1), cB1 = exp2f(m1x - mf1);
            float lf0 = lA * cA0 + l1w * cB0;
            float lf1 = lB * cA1 + l1x * cB1;
            int mlb = ((e * 4 + by) * 64 + qt) * 64;
            if (q4 == 0) {
                g_pm[mlb + mrow] = mf0; g_pm[mlb + mrow + 8] = mf1;
                g_pl[mlb + mrow] = lf0; g_pl[mlb + mrow + 8] = lf1;
            }
            size_t pob = ((size_t)(e * 4 + by) * 64 + qt) * 4096;
#pragma unroll
            for (int nt = 0; nt < 8; nt++) {
                int cb = nt * 8 + 2 * q4;
                float2 v0 = *(float2*)&Om[mrow * 64 + cb];
                *(float2*)&g_po[pob + mrow * 64 + cb] =
                    make_float2(o[nt][0] * cA0 + v0.x * cB0, o[nt][1] * cA0 + v0.y * cB0);
                float2 v1 = *(float2*)&Om[(mrow + 8) * 64 + cb];
                *(float2*)&g_po[pob + (mrow + 8) * 64 + cb] =
                    make_float2(o[nt][2] * cA1 + v1.x * cB1, o[nt][3] * cA1 + v1.y * cB1);
            }
        }
        __syncthreads();
    }
}

// ---------------------------------------------------------------------------
// Merge the two parity partials -> final normalized output.
// ---------------------------------------------------------------------------
__global__ void merge_kernel(float* __restrict__ out)
{
    int idx = blockIdx.x * 256 + threadIdx.x;
    int c2  = idx & 31;
    int row = (idx >> 5) & 63;
    int qt  = (idx >> 11) & 63;
    int b   = idx >> 17;
    int mlb = (b * 64 + qt) * 64 + row;
    float m0 = g_pm[mlb],         l0 = g_pl[mlb];
    float m1 = g_pm[mlb + 16384], l1 = g_pl[mlb + 16384];
    float mf = fmaxf(m0, m1);
    float c0 = exp2f(m0 - mf), c1 = exp2f(m1 - mf);
    float inv = 1.f / (l0 * c0 + l1 * c1);
    size_t p0 = ((size_t)(b * 64) + qt) * 4096 + row * 64 + 2 * c2;
    float2 a = *(float2*)&g_po[p0];
    float2 bb = *(float2*)&g_po[p0 + 1048576];
    float2 r = make_float2((a.x * c0 + bb.x * c1) * inv, (a.y * c0 + bb.y * c1) * inv);
    *(float2*)&out[((size_t)b * 4096 + qt * 64 + row) * 64 + 2 * c2] = r;
}

// ---------------------------------------------------------------------------
extern "C" void kernel_launch(void* const* d_in, const int* in_sizes, int n_in,
                              void* d_out, int out_size)
{
    const float* x  = (const float*)d_in[0];
    const float* Wk = (const float*)d_in[1];
    const float* Wq = (const float*)d_in[2];
    const float* Wv = (const float*)d_in[3];
    float* out = (float*)d_out;

    cudaFuncSetAttribute(proj_kernel, cudaFuncAttributeMaxDynamicSharedMemorySize, PJ_SMEM);
    cudaFuncSetAttribute(attn_kernel, cudaFuncAttributeMaxDynamicSharedMemorySize, AT_SMEM);

    cvtw_kernel<<<768, 256>>>(Wq, Wk, Wv);
    proj_kernel<<<(Bn * Tn) / 64, 256, PJ_SMEM>>>(x);
    attn_kernel<<<dim3(64, Bn), 256, AT_SMEM>>>();
    merge_kernel<<<2048, 256>>>(out);
}

// round 6
// speedup vs baseline: 7.8400x; 1.0610x over previous
#include <cuda_runtime.h>
#include <cuda_fp16.h>
#include <cstdint>

#define Bn 4
#define Tn 4096
#define Cn 1024
#define Hn 64

// fp16 scratch. g_q has 0.125*log2(e) folded (via Wq). g_vt is V TRANSPOSED [b][h][t].
__device__ __align__(16) __half g_q[Bn * Tn * Hn];
__device__ __align__(16) __half g_k[Bn * Tn * Hn];
__device__ __align__(16) __half g_vt[Bn * Hn * Tn];
__device__ __align__(16) __half g_wt[192 * 1024];   // W transposed fp16: [col][k]
// Split-KV partials (fp32): [e][b][qt][row][col] / [e][b][qt][row]
__device__ __align__(16) float g_po[2 * 4 * 64 * 64 * 64];
__device__ float g_pm[2 * 4 * 64 * 64];
__device__ float g_pl[2 * 4 * 64 * 64];

__device__ __forceinline__ void mmah(float* c, const uint32_t* a, const uint32_t* b) {
    asm volatile(
        "mma.sync.aligned.m16n8k16.row.col.f32.f16.f16.f32 "
        "{%0,%1,%2,%3}, {%4,%5,%6,%7}, {%8,%9}, {%0,%1,%2,%3};"
        : "+f"(c[0]), "+f"(c[1]), "+f"(c[2]), "+f"(c[3])
        : "r"(a[0]), "r"(a[1]), "r"(a[2]), "r"(a[3]), "r"(b[0]), "r"(b[1]));
}

__device__ __forceinline__ void cpa16(void* dst, const void* src) {
    uint32_t d = (uint32_t)__cvta_generic_to_shared(dst);
    asm volatile("cp.async.cg.shared.global [%0], [%1], 16;" :: "r"(d), "l"(src));
}
#define CP_COMMIT() asm volatile("cp.async.commit_group;")
#define CP_WAIT0()  asm volatile("cp.async.wait_group 0;")

__device__ __forceinline__ uint32_t ex2h2(float a, float b) {
    __half2 h = __floats2half2_rn(a, b);
    uint32_t x = *reinterpret_cast<uint32_t*>(&h), d;
    asm("ex2.approx.f16x2 %0, %1;" : "=r"(d) : "r"(x));
    return d;
}

// ---------------------------------------------------------------------------
// W pre-convert, transposed: g_wt[c][k]; c<64 -> Wq*QS, <128 -> Wk, <192 -> Wv.
// ---------------------------------------------------------------------------
__global__ void cvtw_kernel(const float* __restrict__ Wq,
                            const float* __restrict__ Wk,
                            const float* __restrict__ Wv)
{
    const float QS = 0.125f * 1.44269504088896f;
    int i = blockIdx.x * 256 + threadIdx.x;        // i = c*1024 + k
    if (i >= 192 * 1024) return;
    int c = i >> 10, k = i & 1023;
    float v;
    if (c < 64)       v = Wq[k * 64 + c] * QS;
    else if (c < 128) v = Wk[k * 64 + (c - 64)];
    else              v = Wv[k * 64 + (c - 128)];
    g_wt[i] = __float2half_rn(v);
}

// ---------------------------------------------------------------------------
// Projection: y = x @ {Wq*s, Wk, Wv}, fp16 m16n8k16. M=16384, K=1024, N=192.
// ---------------------------------------------------------------------------
#define PJ_SMEM ((2 * 2560 + 2 * 7680) * 2)

__global__ __launch_bounds__(256, 2) void proj_kernel(const float* __restrict__ x)
{
    extern __shared__ __half smh[];
    __half* xs = smh;               // 2 x [64][40]
    __half* ws = smh + 2 * 2560;    // 2 x [192][40]

    const int tid = threadIdx.x;
    const int lane = tid & 31, wid = tid >> 5;
    const int m0 = blockIdx.x * 64;
    const int g = lane >> 2, q4 = lane & 3;

    float acc[4][3][4];
#pragma unroll
    for (int mt = 0; mt < 4; mt++)
#pragma unroll
        for (int nt = 0; nt < 3; nt++)
#pragma unroll
            for (int i = 0; i < 4; i++) acc[mt][nt][i] = 0.f;

#pragma unroll
    for (int i = 0; i < 3; i++) {
        int idx = tid + i * 256;
        int n = idx >> 2, cf = (idx & 3) * 8;
        cpa16(&ws[n * 40 + cf], &g_wt[n * 1024 + cf]);
    }
    CP_COMMIT();
    float4 xr[2];
#pragma unroll
    for (int i = 0; i < 2; i++) {
        int idx = tid + i * 256;
        int r = idx >> 3, c4 = (idx & 7) * 4;
        xr[i] = *(const float4*)&x[(size_t)(m0 + r) * Cn + c4];
    }
#pragma unroll
    for (int i = 0; i < 2; i++) {
        int idx = tid + i * 256;
        int r = idx >> 3, c4 = (idx & 7) * 4;
        *(__half2*)&xs[r * 40 + c4]     = __floats2half2_rn(xr[i].x, xr[i].y);
        *(__half2*)&xs[r * 40 + c4 + 2] = __floats2half2_rn(xr[i].z, xr[i].w);
    }

    for (int j = 0; j < 32; j++) {
        __half* xsj = xs + (j & 1) * 2560;
        __half* wsj = ws + (j & 1) * 7680;
        CP_WAIT0();
        __syncthreads();
        if (j < 31) {
            int k0n = (j + 1) * 32;
            __half* wn = ws + ((j + 1) & 1) * 7680;
#pragma unroll
            for (int i = 0; i < 3; i++) {
                int idx = tid + i * 256;
                int n = idx >> 2, cf = (idx & 3) * 8;
                cpa16(&wn[n * 40 + cf], &g_wt[n * 1024 + k0n + cf]);
            }
            CP_COMMIT();
#pragma unroll
            for (int i = 0; i < 2; i++) {
                int idx = tid + i * 256;
                int r = idx >> 3, c4 = (idx & 7) * 4;
                xr[i] = *(const float4*)&x[(size_t)(m0 + r) * Cn + k0n + c4];
            }
        }

#pragma unroll
        for (int k16 = 0; k16 < 2; k16++) {
            int kk = k16 * 16 + 2 * q4;
            uint32_t bfr[3][2];
#pragma unroll
            for (int nt = 0; nt < 3; nt++) {
                int n = wid * 24 + nt * 8 + g;
                bfr[nt][0] = *(const uint32_t*)&wsj[n * 40 + kk];
                bfr[nt][1] = *(const uint32_t*)&wsj[n * 40 + kk + 8];
            }
#pragma unroll
            for (int mt = 0; mt < 4; mt++) {
                int r = mt * 16 + g;
                uint32_t a[4] = { *(const uint32_t*)&xsj[r * 40 + kk],
                                  *(const uint32_t*)&xsj[(r + 8) * 40 + kk],
                                  *(const uint32_t*)&xsj[r * 40 + kk + 8],
                                  *(const uint32_t*)&xsj[(r + 8) * 40 + kk + 8] };
#pragma unroll
                for (int nt = 0; nt < 3; nt++) mmah(acc[mt][nt], a, bfr[nt]);
            }
        }

        if (j < 31) {
            __half* xn = xs + ((j + 1) & 1) * 2560;
#pragma unroll
            for (int i = 0; i < 2; i++) {
                int idx = tid + i * 256;
                int r = idx >> 3, c4 = (idx & 7) * 4;
                *(__half2*)&xn[r * 40 + c4]     = __floats2half2_rn(xr[i].x, xr[i].y);
                *(__half2*)&xn[r * 40 + c4 + 2] = __floats2half2_rn(xr[i].z, xr[i].w);
            }
        }
    }

    const int bb = m0 >> 12, t0 = m0 & 4095;
#pragma unroll
    for (int mt = 0; mt < 4; mt++)
#pragma unroll
        for (int nt = 0; nt < 3; nt++) {
            int col = wid * 24 + nt * 8;
            if (col < 128) {
                __half* dst = (col < 64) ? g_q : g_k;
                int h = (col & 63) + 2 * q4;
                size_t r = (size_t)(m0 + mt * 16 + g) * 64 + h;
                *(__half2*)&dst[r] = __floats2half2_rn(acc[mt][nt][0], acc[mt][nt][1]);
                *(__half2*)&dst[r + 8 * 64] = __floats2half2_rn(acc[mt][nt][2], acc[mt][nt][3]);
            } else {
                int h = (col - 128) + 2 * q4;
                int tr = t0 + mt * 16 + g;
                __half* vp = &g_vt[((size_t)bb * 64 + h) * 4096 + tr];
                vp[0]        = __float2half_rn(acc[mt][nt][0]);
                vp[4096]     = __float2half_rn(acc[mt][nt][1]);
                vp[8]        = __float2half_rn(acc[mt][nt][2]);
                vp[4096 + 8] = __float2half_rn(acc[mt][nt][3]);
            }
        }
}

// ---------------------------------------------------------------------------
// Causal flash attention, fp16 m16n8k16, parity split-KV, per-warp softmax.
// P kept in registers (C-frag == A-frag layout); row sums via ones-MMA;
// exp via ex2.approx.f16x2. One __syncthreads per step.
// ---------------------------------------------------------------------------
#define AT_SMEM (5 * 4608 * 2)

__global__ __launch_bounds__(256, 2) void attn_kernel()
{
    extern __shared__ __half smh[];
    __half* ks = smh;                 // 2 x [64 key][72]
    __half* vt = smh + 2 * 4608;      // 2 x [64 h][72]  (V^T: [h][key])
    __half* qs = smh + 4 * 4608;      // [64 row][72]
    float* Om  = (float*)vt;          // epilogue reuse [64][64]
    float* m1a = (float*)ks;          // epilogue reuse [64]
    float* l1a = m1a + 64;

    const int tid = threadIdx.x, lane = tid & 31, wid = tid >> 5;
    const int wc = wid >> 2, wr = wid & 3;
    const int g = lane >> 2, q4 = lane & 3;
    const int mrow = wr * 16 + g;
    const int e = blockIdx.x & 1, p = blockIdx.x >> 1;
    const int by = blockIdx.y;
    const size_t base = (size_t)by * Tn * Hn;
    const uint32_t ONES = 0x3C003C00u;
    const uint32_t onesb[2] = { ONES, ONES };

    for (int pass = 0; pass < 2; pass++) {
        const int qt = pass ? 63 - p : p;

#pragma unroll
        for (int i = 0; i < 2; i++) {
            int idx = tid + i * 256;
            int r = idx >> 3, cf = (idx & 7) * 8;
            cpa16(&qs[r * 72 + cf], &g_q[base + (size_t)(qt * 64 + r) * 64 + cf]);
        }
        if (e <= qt) {
#pragma unroll
            for (int i = 0; i < 2; i++) {
                int idx = tid + i * 256;
                int r = idx >> 3, cf = (idx & 7) * 8;
                cpa16(&ks[r * 72 + cf], &g_k[base + (size_t)(e * 64 + r) * 64 + cf]);
                cpa16(&vt[r * 72 + cf], &g_vt[((size_t)by * 64 + r) * 4096 + e * 64 + cf]);
            }
        }
        CP_COMMIT();

        float o[8][4], ol[4];
#pragma unroll
        for (int nt = 0; nt < 8; nt++)
#pragma unroll
            for (int i = 0; i < 4; i++) o[nt][i] = 0.f;
#pragma unroll
        for (int i = 0; i < 4; i++) ol[i] = 0.f;
        float mA = -1e30f, mB = -1e30f;

        int t = 0;
        for (int j = e; j <= qt; j += 2, t++) {
            __half* kb = ks + (t & 1) * 4608;
            __half* vb = vt + (t & 1) * 4608;
            CP_WAIT0();
            __syncthreads();
            if (j + 2 <= qt) {
                __half* kn = ks + ((t + 1) & 1) * 4608;
                __half* vn = vt + ((t + 1) & 1) * 4608;
#pragma unroll
                for (int i = 0; i < 2; i++) {
                    int idx = tid + i * 256;
                    int r = idx >> 3, cf = (idx & 7) * 8;
                    cpa16(&kn[r * 72 + cf], &g_k[base + (size_t)((j + 2) * 64 + r) * 64 + cf]);
                    cpa16(&vn[r * 72 + cf], &g_vt[((size_t)by * 64 + r) * 4096 + (j + 2) * 64 + cf]);
                }
                CP_COMMIT();
            }

            // S = Q K^T over this warp's 32-key half
            float s[4][4];
#pragma unroll
            for (int nt = 0; nt < 4; nt++)
#pragma unroll
                for (int i = 0; i < 4; i++) s[nt][i] = 0.f;
#pragma unroll
            for (int k16 = 0; k16 < 4; k16++) {
                int kk = k16 * 16 + 2 * q4;
                uint32_t a[4] = { *(const uint32_t*)&qs[mrow * 72 + kk],
                                  *(const uint32_t*)&qs[(mrow + 8) * 72 + kk],
                                  *(const uint32_t*)&qs[mrow * 72 + kk + 8],
                                  *(const uint32_t*)&qs[(mrow + 8) * 72 + kk + 8] };
#pragma unroll
                for (int nt = 0; nt < 4; nt++) {
                    int n = wc * 32 + nt * 8 + g;
                    uint32_t b2[2] = { *(const uint32_t*)&kb[n * 72 + kk],
                                       *(const uint32_t*)&kb[n * 72 + kk + 8] };
                    mmah(s[nt], a, b2);
                }
            }
            if (j == qt) {
#pragma unroll
                for (int nt = 0; nt < 4; nt++) {
                    int c0 = wc * 32 + nt * 8 + 2 * q4;
                    if (c0 > mrow)         s[nt][0] = -1e30f;
                    if (c0 + 1 > mrow)     s[nt][1] = -1e30f;
                    if (c0 > mrow + 8)     s[nt][2] = -1e30f;
                    if (c0 + 1 > mrow + 8) s[nt][3] = -1e30f;
                }
            }

            // row max (packed half2 reduce over the lane quad)
            float mx0 = -1e30f, mx1 = -1e30f;
#pragma unroll
            for (int nt = 0; nt < 4; nt++) {
                mx0 = fmaxf(mx0, fmaxf(s[nt][0], s[nt][1]));
                mx1 = fmaxf(mx1, fmaxf(s[nt][2], s[nt][3]));
            }
            __half2 hmx = __floats2half2_rn(mx0, mx1);
            uint32_t um = *reinterpret_cast<uint32_t*>(&hmx);
            uint32_t um1 = __shfl_xor_sync(~0u, um, 1);
            hmx = __hmax2(hmx, *reinterpret_cast<__half2*>(&um1));
            um = *reinterpret_cast<uint32_t*>(&hmx);
            uint32_t um2 = __shfl_xor_sync(~0u, um, 2);
            hmx = __hmax2(hmx, *reinterpret_cast<__half2*>(&um2));
            float2 mxf = __half22float2(hmx);
            float mn0 = fmaxf(mA, mxf.x), mn1 = fmaxf(mB, mxf.y);
            float corr0 = exp2f(mA - mn0), corr1 = exp2f(mB - mn1);
            mA = mn0; mB = mn1;

            // P = 2^(S - mn), fp16x2, kept in registers (A-fragment layout)
            uint32_t ph0[4], ph1[4];
#pragma unroll
            for (int nt = 0; nt < 4; nt++) {
                ph0[nt] = ex2h2(s[nt][0] - mn0, s[nt][1] - mn0);
                ph1[nt] = ex2h2(s[nt][2] - mn1, s[nt][3] - mn1);
            }

            // rescale accumulators
#pragma unroll
            for (int nt = 0; nt < 8; nt++) {
                o[nt][0] *= corr0; o[nt][1] *= corr0;
                o[nt][2] *= corr1; o[nt][3] *= corr1;
            }
            ol[0] *= corr0; ol[1] *= corr0; ol[2] *= corr1; ol[3] *= corr1;

            // O += P V; l += P 1
#pragma unroll
            for (int kg = 0; kg < 2; kg++) {
                int kk = kg * 16 + 2 * q4;
                uint32_t a[4] = { ph0[2 * kg], ph1[2 * kg], ph0[2 * kg + 1], ph1[2 * kg + 1] };
                mmah(ol, a, onesb);
#pragma unroll
                for (int nt = 0; nt < 8; nt++) {
                    int h = nt * 8 + g;
                    uint32_t b2[2] = { *(const uint32_t*)&vb[h * 72 + wc * 32 + kk],
                                       *(const uint32_t*)&vb[h * 72 + wc * 32 + kk + 8] };
                    mmah(o[nt], a, b2);
                }
            }
        }
        float lA = ol[0], lB = ol[2];

        // epilogue: merge wc halves, write unnormalized parity partial
        __syncthreads();
        if (wc == 1) {
            if (q4 == 0) {
                m1a[mrow] = mA; m1a[mrow + 8] = mB;
                l1a[mrow] = lA; l1a[mrow + 8] = lB;
            }
#pragma unroll
            for (int nt = 0; nt < 8; nt++) {
                int cb = nt * 8 + 2 * q4;
                *(float2*)&Om[mrow * 64 + cb]       = make_float2(o[nt][0], o[nt][1]);
                *(float2*)&Om[(mrow + 8) * 64 + cb] = make_float2(o[nt][2], o[nt][3]);
            }
        }
        __syncthreads();
        if (wc == 0) {
            float m1w = m1a[mrow], l1w = l1a[mrow];
            float m1x = m1a[mrow + 8], l1x = l1a[mrow + 8];
            float mf0 = fmaxf(mA, m1w), mf1 = fmaxf(mB, m1x);
            float cA0 = exp2f(mA - mf0), cB0 = exp2f(m1w - mf0);
            float cA1 = exp2f(mB - mf1), cB1 = exp2f(m1x - mf1);
            float lf0 = lA * cA0 + l1w * cB0;
            float lf1 = lB * cA1 + l1x * cB1;
            int mlb = ((e * 4 + by) * 64 + qt) * 64;
            if (q4 == 0) {
                g_pm[mlb + mrow] = mf0; g_pm[mlb + mrow + 8] = mf1;
                g_pl[mlb + mrow] = lf0; g_pl[mlb + mrow + 8] = lf1;
            }
            size_t pob = ((size_t)(e * 4 + by) * 64 + qt) * 4096;
#pragma unroll
            for (int nt = 0; nt < 8; nt++) {
                int cb = nt * 8 + 2 * q4;
                float2 v0 = *(float2*)&Om[mrow * 64 + cb];
                *(float2*)&g_po[pob + mrow * 64 + cb] =
                    make_float2(o[nt][0] * cA0 + v0.x * cB0, o[nt][1] * cA0 + v0.y * cB0);
                float2 v1 = *(float2*)&Om[(mrow + 8) * 64 + cb];
                *(float2*)&g_po[pob + (mrow + 8) * 64 + cb] =
                    make_float2(o[nt][2] * cA1 + v1.x * cB1, o[nt][3] * cA1 + v1.y * cB1);
            }
        }
        __syncthreads();
    }
}

// ---------------------------------------------------------------------------
// Merge the two parity partials -> final normalized output.
// ---------------------------------------------------------------------------
__global__ void merge_kernel(float* __restrict__ out)
{
    int idx = blockIdx.x * 256 + threadIdx.x;
    int c2  = idx & 31;
    int row = (idx >> 5) & 63;
    int qt  = (idx >> 11) & 63;
    int b   = idx >> 17;
    int mlb = (b * 64 + qt) * 64 + row;
    float m0 = g_pm[mlb],         l0 = g_pl[mlb];
    float m1 = g_pm[mlb + 16384], l1 = g_pl[mlb + 16384];
    float mf = fmaxf(m0, m1);
    float c0 = exp2f(m0 - mf), c1 = exp2f(m1 - mf);
    float inv = 1.f / (l0 * c0 + l1 * c1);
    size_t p0 = ((size_t)(b * 64) + qt) * 4096 + row * 64 + 2 * c2;
    float2 a = *(float2*)&g_po[p0];
    float2 bb = *(float2*)&g_po[p0 + 1048576];
    float2 r = make_float2((a.x * c0 + bb.x * c1) * inv, (a.y * c0 + bb.y * c1) * inv);
    *(float2*)&out[((size_t)b * 4096 + qt * 64 + row) * 64 + 2 * c2] = r;
}

// ---------------------------------------------------------------------------
extern "C" void kernel_launch(void* const* d_in, const int* in_sizes, int n_in,
                              void* d_out, int out_size)
{
    const float* x  = (const float*)d_in[0];
    const float* Wk = (const float*)d_in[1];
    const float* Wq = (const float*)d_in[2];
    const float* Wv = (const float*)d_in[3];
    float* out = (float*)d_out;

    cudaFuncSetAttribute(proj_kernel, cudaFuncAttributeMaxDynamicSharedMemorySize, PJ_SMEM);
    cudaFuncSetAttribute(attn_kernel, cudaFuncAttributeMaxDynamicSharedMemorySize, AT_SMEM);

    cvtw_kernel<<<768, 256>>>(Wq, Wk, Wv);
    proj_kernel<<<(Bn * Tn) / 64, 256, PJ_SMEM>>>(x);
    attn_kernel<<<dim3(64, Bn), 256, AT_SMEM>>>();
    merge_kernel<<<2048, 256>>>(out);
}

// round 7
// speedup vs baseline: 8.7044x; 1.1103x over previous
#include <cuda_runtime.h>
#include <cuda_fp16.h>
#include <cstdint>

#define Bn 4
#define Tn 4096
#define Cn 1024
#define Hn 64

// fp16 scratch. g_q has 0.125*log2(e) folded (via Wq). g_vt is V TRANSPOSED [b][h][t].
__device__ __align__(16) __half g_q[Bn * Tn * Hn];
__device__ __align__(16) __half g_k[Bn * Tn * Hn];
__device__ __align__(16) __half g_vt[Bn * Hn * Tn];
__device__ __align__(16) __half g_wt[192 * 1024];   // W transposed fp16: [col][k]
// Split-KV partials: O in fp16, stats fp32. [e][b][qt][row][col] / [e][b][qt][row]
__device__ __align__(16) __half g_po[2 * 4 * 64 * 64 * 64];
__device__ float g_pm[2 * 4 * 64 * 64];
__device__ float g_pl[2 * 4 * 64 * 64];

__device__ __forceinline__ void mmah(float* c, const uint32_t* a, const uint32_t* b) {
    asm volatile(
        "mma.sync.aligned.m16n8k16.row.col.f32.f16.f16.f32 "
        "{%0,%1,%2,%3}, {%4,%5,%6,%7}, {%8,%9}, {%0,%1,%2,%3};"
        : "+f"(c[0]), "+f"(c[1]), "+f"(c[2]), "+f"(c[3])
        : "r"(a[0]), "r"(a[1]), "r"(a[2]), "r"(a[3]), "r"(b[0]), "r"(b[1]));
}

__device__ __forceinline__ void cpa16(void* dst, const void* src) {
    uint32_t d = (uint32_t)__cvta_generic_to_shared(dst);
    asm volatile("cp.async.cg.shared.global [%0], [%1], 16;" :: "r"(d), "l"(src));
}
#define CP_COMMIT() asm volatile("cp.async.commit_group;")
#define CP_WAIT0()  asm volatile("cp.async.wait_group 0;")

__device__ __forceinline__ void ldsm4(uint32_t& r0, uint32_t& r1, uint32_t& r2, uint32_t& r3,
                                      uint32_t a) {
    asm volatile("ldmatrix.sync.aligned.m8n8.x4.shared.b16 {%0,%1,%2,%3}, [%4];"
        : "=r"(r0), "=r"(r1), "=r"(r2), "=r"(r3) : "r"(a));
}

__device__ __forceinline__ uint32_t ex2h2(float a, float b) {
    __half2 h = __floats2half2_rn(a, b);
    uint32_t x = *reinterpret_cast<uint32_t*>(&h), d;
    asm("ex2.approx.f16x2 %0, %1;" : "=r"(d) : "r"(x));
    return d;
}

// ---------------------------------------------------------------------------
// W pre-convert, transposed: g_wt[c][k]; c<64 -> Wq*QS, <128 -> Wk, <192 -> Wv.
// ---------------------------------------------------------------------------
__global__ void cvtw_kernel(const float* __restrict__ Wq,
                            const float* __restrict__ Wk,
                            const float* __restrict__ Wv)
{
    const float QS = 0.125f * 1.44269504088896f;
    int i = blockIdx.x * 256 + threadIdx.x;
    if (i >= 192 * 1024) return;
    int c = i >> 10, k = i & 1023;
    float v;
    if (c < 64)       v = Wq[k * 64 + c] * QS;
    else if (c < 128) v = Wk[k * 64 + (c - 64)];
    else              v = Wv[k * 64 + (c - 128)];
    g_wt[i] = __float2half_rn(v);
}

// ---------------------------------------------------------------------------
// Projection: y = x @ {Wq*s, Wk, Wv}, fp16 m16n8k16. M=16384, K=1024, N=192.
// ---------------------------------------------------------------------------
#define PJ_SMEM ((2 * 2560 + 2 * 7680) * 2)

__global__ __launch_bounds__(256, 2) void proj_kernel(const float* __restrict__ x)
{
    extern __shared__ __half smh[];
    __half* xs = smh;               // 2 x [64][40]
    __half* ws = smh + 2 * 2560;    // 2 x [192][40]

    const int tid = threadIdx.x;
    const int lane = tid & 31, wid = tid >> 5;
    const int m0 = blockIdx.x * 64;
    const int g = lane >> 2, q4 = lane & 3;

    float acc[4][3][4];
#pragma unroll
    for (int mt = 0; mt < 4; mt++)
#pragma unroll
        for (int nt = 0; nt < 3; nt++)
#pragma unroll
            for (int i = 0; i < 4; i++) acc[mt][nt][i] = 0.f;

#pragma unroll
    for (int i = 0; i < 3; i++) {
        int idx = tid + i * 256;
        int n = idx >> 2, cf = (idx & 3) * 8;
        cpa16(&ws[n * 40 + cf], &g_wt[n * 1024 + cf]);
    }
    CP_COMMIT();
    float4 xr[2];
#pragma unroll
    for (int i = 0; i < 2; i++) {
        int idx = tid + i * 256;
        int r = idx >> 3, c4 = (idx & 7) * 4;
        xr[i] = *(const float4*)&x[(size_t)(m0 + r) * Cn + c4];
    }
#pragma unroll
    for (int i = 0; i < 2; i++) {
        int idx = tid + i * 256;
        int r = idx >> 3, c4 = (idx & 7) * 4;
        *(__half2*)&xs[r * 40 + c4]     = __floats2half2_rn(xr[i].x, xr[i].y);
        *(__half2*)&xs[r * 40 + c4 + 2] = __floats2half2_rn(xr[i].z, xr[i].w);
    }

    for (int j = 0; j < 32; j++) {
        __half* xsj = xs + (j & 1) * 2560;
        __half* wsj = ws + (j & 1) * 7680;
        CP_WAIT0();
        __syncthreads();
        if (j < 31) {
            int k0n = (j + 1) * 32;
            __half* wn = ws + ((j + 1) & 1) * 7680;
#pragma unroll
            for (int i = 0; i < 3; i++) {
                int idx = tid + i * 256;
                int n = idx >> 2, cf = (idx & 3) * 8;
                cpa16(&wn[n * 40 + cf], &g_wt[n * 1024 + k0n + cf]);
            }
            CP_COMMIT();
#pragma unroll
            for (int i = 0; i < 2; i++) {
                int idx = tid + i * 256;
                int r = idx >> 3, c4 = (idx & 7) * 4;
                xr[i] = *(const float4*)&x[(size_t)(m0 + r) * Cn + k0n + c4];
            }
        }

#pragma unroll
        for (int k16 = 0; k16 < 2; k16++) {
            int kk = k16 * 16 + 2 * q4;
            uint32_t bfr[3][2];
#pragma unroll
            for (int nt = 0; nt < 3; nt++) {
                int n = wid * 24 + nt * 8 + g;
                bfr[nt][0] = *(const uint32_t*)&wsj[n * 40 + kk];
                bfr[nt][1] = *(const uint32_t*)&wsj[n * 40 + kk + 8];
            }
#pragma unroll
            for (int mt = 0; mt < 4; mt++) {
                int r = mt * 16 + g;
                uint32_t a[4] = { *(const uint32_t*)&xsj[r * 40 + kk],
                                  *(const uint32_t*)&xsj[(r + 8) * 40 + kk],
                                  *(const uint32_t*)&xsj[r * 40 + kk + 8],
                                  *(const uint32_t*)&xsj[(r + 8) * 40 + kk + 8] };
#pragma unroll
                for (int nt = 0; nt < 3; nt++) mmah(acc[mt][nt], a, bfr[nt]);
            }
        }

        if (j < 31) {
            __half* xn = xs + ((j + 1) & 1) * 2560;
#pragma unroll
            for (int i = 0; i < 2; i++) {
                int idx = tid + i * 256;
                int r = idx >> 3, c4 = (idx & 7) * 4;
                *(__half2*)&xn[r * 40 + c4]     = __floats2half2_rn(xr[i].x, xr[i].y);
                *(__half2*)&xn[r * 40 + c4 + 2] = __floats2half2_rn(xr[i].z, xr[i].w);
            }
        }
    }

    const int bb = m0 >> 12, t0 = m0 & 4095;
#pragma unroll
    for (int mt = 0; mt < 4; mt++)
#pragma unroll
        for (int nt = 0; nt < 3; nt++) {
            int col = wid * 24 + nt * 8;
            if (col < 128) {
                __half* dst = (col < 64) ? g_q : g_k;
                int h = (col & 63) + 2 * q4;
                size_t r = (size_t)(m0 + mt * 16 + g) * 64 + h;
                *(__half2*)&dst[r] = __floats2half2_rn(acc[mt][nt][0], acc[mt][nt][1]);
                *(__half2*)&dst[r + 8 * 64] = __floats2half2_rn(acc[mt][nt][2], acc[mt][nt][3]);
            } else {
                int h = (col - 128) + 2 * q4;
                int tr = t0 + mt * 16 + g;
                __half* vp = &g_vt[((size_t)bb * 64 + h) * 4096 + tr];
                vp[0]        = __float2half_rn(acc[mt][nt][0]);
                vp[4096]     = __float2half_rn(acc[mt][nt][1]);
                vp[8]        = __float2half_rn(acc[mt][nt][2]);
                vp[4096 + 8] = __float2half_rn(acc[mt][nt][3]);
            }
        }
}

// ---------------------------------------------------------------------------
// Causal flash attention, fp16 m16n8k16, parity split-KV, per-warp softmax.
// Q fragments hoisted to registers; K/V fragments via ldmatrix.x4;
// P in registers; row sums via ones-MMA; exp via ex2.approx.f16x2.
// ---------------------------------------------------------------------------
#define AT_SMEM (5 * 4608 * 2)

__global__ __launch_bounds__(256, 2) void attn_kernel()
{
    extern __shared__ __half smh[];
    __half* ks = smh;                 // 2 x [64 key][72]
    __half* vt = smh + 2 * 4608;      // 2 x [64 h][72]  (V^T: [h][key])
    __half* qs = smh + 4 * 4608;      // [64 row][72]
    float* Om  = (float*)vt;          // epilogue reuse [64][64]
    float* m1a = (float*)ks;          // epilogue reuse [64]
    float* l1a = m1a + 64;

    const int tid = threadIdx.x, lane = tid & 31, wid = tid >> 5;
    const int wc = wid >> 2, wr = wid & 3;
    const int g = lane >> 2, q4 = lane & 3;
    const int mrow = wr * 16 + g;
    const int e = blockIdx.x & 1, p = blockIdx.x >> 1;
    const int by = blockIdx.y;
    const size_t base = (size_t)by * Tn * Hn;
    const uint32_t ONES = 0x3C003C00u;
    const uint32_t onesb[2] = { ONES, ONES };

    // per-lane ldmatrix row offsets (in halves)
    const int mt8 = lane >> 3, rw = lane & 7;
    const int koff = (wc * 32 + (mt8 >> 1) * 8 + rw) * 72 + (mt8 & 1) * 8;
    const int voff = ((mt8 >> 1) * 8 + rw) * 72 + wc * 32 + (mt8 & 1) * 8;
    const int qoff = (wr * 16 + (mt8 & 1) * 8 + rw) * 72 + (mt8 >> 1) * 8;

    for (int pass = 0; pass < 2; pass++) {
        const int qt = pass ? 63 - p : p;

#pragma unroll
        for (int i = 0; i < 2; i++) {
            int idx = tid + i * 256;
            int r = idx >> 3, cf = (idx & 7) * 8;
            cpa16(&qs[r * 72 + cf], &g_q[base + (size_t)(qt * 64 + r) * 64 + cf]);
        }
        if (e <= qt) {
#pragma unroll
            for (int i = 0; i < 2; i++) {
                int idx = tid + i * 256;
                int r = idx >> 3, cf = (idx & 7) * 8;
                cpa16(&ks[r * 72 + cf], &g_k[base + (size_t)(e * 64 + r) * 64 + cf]);
                cpa16(&vt[r * 72 + cf], &g_vt[((size_t)by * 64 + r) * 4096 + e * 64 + cf]);
            }
        }
        CP_COMMIT();
        CP_WAIT0();
        __syncthreads();

        // hoist Q fragments (loop-invariant)
        uint32_t qa[4][4];
        {
            uint32_t qsa = (uint32_t)__cvta_generic_to_shared(qs) + 2 * qoff;
#pragma unroll
            for (int k16 = 0; k16 < 4; k16++)
                ldsm4(qa[k16][0], qa[k16][1], qa[k16][2], qa[k16][3], qsa + k16 * 32);
        }

        float o[8][4], ol[4];
#pragma unroll
        for (int nt = 0; nt < 8; nt++)
#pragma unroll
            for (int i = 0; i < 4; i++) o[nt][i] = 0.f;
#pragma unroll
        for (int i = 0; i < 4; i++) ol[i] = 0.f;
        float mA = -1e30f, mB = -1e30f;

        int t = 0;
        for (int j = e; j <= qt; j += 2, t++) {
            __half* kb = ks + (t & 1) * 4608;
            __half* vb = vt + (t & 1) * 4608;
            CP_WAIT0();
            __syncthreads();
            if (j + 2 <= qt) {
                __half* kn = ks + ((t + 1) & 1) * 4608;
                __half* vn = vt + ((t + 1) & 1) * 4608;
#pragma unroll
                for (int i = 0; i < 2; i++) {
                    int idx = tid + i * 256;
                    int r = idx >> 3, cf = (idx & 7) * 8;
                    cpa16(&kn[r * 72 + cf], &g_k[base + (size_t)((j + 2) * 64 + r) * 64 + cf]);
                    cpa16(&vn[r * 72 + cf], &g_vt[((size_t)by * 64 + r) * 4096 + (j + 2) * 64 + cf]);
                }
                CP_COMMIT();
            }

            const uint32_t kba = (uint32_t)__cvta_generic_to_shared(kb) + 2 * koff;
            const uint32_t vba = (uint32_t)__cvta_generic_to_shared(vb) + 2 * voff;

            // S = Q K^T over this warp's 32-key half (K frags via ldmatrix)
            float s[4][4];
#pragma unroll
            for (int nt = 0; nt < 4; nt++)
#pragma unroll
                for (int i = 0; i < 4; i++) s[nt][i] = 0.f;
#pragma unroll
            for (int k16 = 0; k16 < 4; k16++) {
#pragma unroll
                for (int a2 = 0; a2 < 2; a2++) {
                    uint32_t b0, b1, b2, b3;
                    ldsm4(b0, b1, b2, b3, kba + 2 * (a2 * 16 * 72) + k16 * 32);
                    uint32_t bb0[2] = { b0, b1 }, bb1[2] = { b2, b3 };
                    mmah(s[2 * a2],     qa[k16], bb0);
                    mmah(s[2 * a2 + 1], qa[k16], bb1);
                }
            }
            if (j == qt) {
#pragma unroll
                for (int nt = 0; nt < 4; nt++) {
                    int c0 = wc * 32 + nt * 8 + 2 * q4;
                    if (c0 > mrow)         s[nt][0] = -1e30f;
                    if (c0 + 1 > mrow)     s[nt][1] = -1e30f;
                    if (c0 > mrow + 8)     s[nt][2] = -1e30f;
                    if (c0 + 1 > mrow + 8) s[nt][3] = -1e30f;
                }
            }

            // row max (packed half2 reduce over lane quad)
            float mx0 = -1e30f, mx1 = -1e30f;
#pragma unroll
            for (int nt = 0; nt < 4; nt++) {
                mx0 = fmaxf(mx0, fmaxf(s[nt][0], s[nt][1]));
                mx1 = fmaxf(mx1, fmaxf(s[nt][2], s[nt][3]));
            }
            __half2 hmx = __floats2half2_rn(mx0, mx1);
            uint32_t um = *reinterpret_cast<uint32_t*>(&hmx);
            uint32_t um1 = __shfl_xor_sync(~0u, um, 1);
            hmx = __hmax2(hmx, *reinterpret_cast<__half2*>(&um1));
            um = *reinterpret_cast<uint32_t*>(&hmx);
            uint32_t um2 = __shfl_xor_sync(~0u, um, 2);
            hmx = __hmax2(hmx, *reinterpret_cast<__half2*>(&um2));
            float2 mxf = __half22float2(hmx);
            float mn0 = fmaxf(mA, mxf.x), mn1 = fmaxf(mB, mxf.y);
            float corr0 = exp2f(mA - mn0), corr1 = exp2f(mB - mn1);
            mA = mn0; mB = mn1;

            // P = 2^(S - mn) in fp16x2 registers (A-fragment layout)
            uint32_t ph0[4], ph1[4];
#pragma unroll
            for (int nt = 0; nt < 4; nt++) {
                ph0[nt] = ex2h2(s[nt][0] - mn0, s[nt][1] - mn0);
                ph1[nt] = ex2h2(s[nt][2] - mn1, s[nt][3] - mn1);
            }

#pragma unroll
            for (int nt = 0; nt < 8; nt++) {
                o[nt][0] *= corr0; o[nt][1] *= corr0;
                o[nt][2] *= corr1; o[nt][3] *= corr1;
            }
            ol[0] *= corr0; ol[1] *= corr0; ol[2] *= corr1; ol[3] *= corr1;

            // O += P V; l += P 1   (V frags via ldmatrix)
#pragma unroll
            for (int kg = 0; kg < 2; kg++) {
                uint32_t a[4] = { ph0[2 * kg], ph1[2 * kg], ph0[2 * kg + 1], ph1[2 * kg + 1] };
                mmah(ol, a, onesb);
#pragma unroll
                for (int vg = 0; vg < 4; vg++) {
                    uint32_t b0, b1, b2, b3;
                    ldsm4(b0, b1, b2, b3, vba + 2 * (vg * 16 * 72) + kg * 32);
                    uint32_t bb0[2] = { b0, b1 }, bb1[2] = { b2, b3 };
                    mmah(o[2 * vg],     a, bb0);
                    mmah(o[2 * vg + 1], a, bb1);
                }
            }
        }
        float lA = ol[0], lB = ol[2];

        // epilogue: merge wc halves, write unnormalized parity partial (fp16)
        __syncthreads();
        if (wc == 1) {
            if (q4 == 0) {
                m1a[mrow] = mA; m1a[mrow + 8] = mB;
                l1a[mrow] = lA; l1a[mrow + 8] = lB;
            }
#pragma unroll
            for (int nt = 0; nt < 8; nt++) {
                int cb = nt * 8 + 2 * q4;
                *(float2*)&Om[mrow * 64 + cb]       = make_float2(o[nt][0], o[nt][1]);
                *(float2*)&Om[(mrow + 8) * 64 + cb] = make_float2(o[nt][2], o[nt][3]);
            }
        }
        __syncthreads();
        if (wc == 0) {
            float m1w = m1a[mrow], l1w = l1a[mrow];
            float m1x = m1a[mrow + 8], l1x = l1a[mrow + 8];
            float mf0 = fmaxf(mA, m1w), mf1 = fmaxf(mB, m1x);
            float cA0 = exp2f(mA - mf0), cB0 = exp2f(m1w - mf0);
            float cA1 = exp2f(mB - mf1), cB1 = exp2f(m1x - mf1);
            float lf0 = lA * cA0 + l1w * cB0;
            float lf1 = lB * cA1 + l1x * cB1;
            int mlb = ((e * 4 + by) * 64 + qt) * 64;
            if (q4 == 0) {
                g_pm[mlb + mrow] = mf0; g_pm[mlb + mrow + 8] = mf1;
                g_pl[mlb + mrow] = lf0; g_pl[mlb + mrow + 8] = lf1;
            }
            size_t pob = ((size_t)(e * 4 + by) * 64 + qt) * 4096;
#pragma unroll
            for (int nt = 0; nt < 8; nt++) {
                int cb = nt * 8 + 2 * q4;
                float2 v0 = *(float2*)&Om[mrow * 64 + cb];
                *(__half2*)&g_po[pob + mrow * 64 + cb] =
                    __floats2half2_rn(o[nt][0] * cA0 + v0.x * cB0, o[nt][1] * cA0 + v0.y * cB0);
                float2 v1 = *(float2*)&Om[(mrow + 8) * 64 + cb];
                *(__half2*)&g_po[pob + (mrow + 8) * 64 + cb] =
                    __floats2half2_rn(o[nt][2] * cA1 + v1.x * cB1, o[nt][3] * cA1 + v1.y * cB1);
            }
        }
        __syncthreads();
    }
}

// ---------------------------------------------------------------------------
// Merge the two parity partials -> final normalized output.
// ---------------------------------------------------------------------------
__global__ void merge_kernel(float* __restrict__ out)
{
    int idx = blockIdx.x * 256 + threadIdx.x;
    int c2  = idx & 31;
    int row = (idx >> 5) & 63;
    int qt  = (idx >> 11) & 63;
    int b   = idx >> 17;
    int mlb = (b * 64 + qt) * 64 + row;
    float m0 = g_pm[mlb],         l0 = g_pl[mlb];
    float m1 = g_pm[mlb + 16384], l1 = g_pl[mlb + 16384];
    float mf = fmaxf(m0, m1);
    float c0 = exp2f(m0 - mf), c1 = exp2f(m1 - mf);
    float inv = 1.f / (l0 * c0 + l1 * c1);
    size_t p0 = ((size_t)(b * 64) + qt) * 4096 + row * 64 + 2 * c2;
    float2 a = __half22float2(*(const __half2*)&g_po[p0]);
    float2 bb = __half22float2(*(const __half2*)&g_po[p0 + 1048576]);
    float2 r = make_float2((a.x * c0 + bb.x * c1) * inv, (a.y * c0 + bb.y * c1) * inv);
    *(float2*)&out[((size_t)b * 4096 + qt * 64 + row) * 64 + 2 * c2] = r;
}

// ---------------------------------------------------------------------------
extern "C" void kernel_launch(void* const* d_in, const int* in_sizes, int n_in,
                              void* d_out, int out_size)
{
    const float* x  = (const float*)d_in[0];
    const float* Wk = (const float*)d_in[1];
    const float* Wq = (const float*)d_in[2];
    const float* Wv = (const float*)d_in[3];
    float* out = (float*)d_out;

    cudaFuncSetAttribute(proj_kernel, cudaFuncAttributeMaxDynamicSharedMemorySize, PJ_SMEM);
    cudaFuncSetAttribute(attn_kernel, cudaFuncAttributeMaxDynamicSharedMemorySize, AT_SMEM);

    cvtw_kernel<<<768, 256>>>(Wq, Wk, Wv);
    proj_kernel<<<(Bn * Tn) / 64, 256, PJ_SMEM>>>(x);
    attn_kernel<<<dim3(64, Bn), 256, AT_SMEM>>>();
    merge_kernel<<<2048, 256>>>(out);
}

// round 8
// speedup vs baseline: 9.9385x; 1.1418x over previous
#include <cuda_runtime.h>
#include <cuda_fp16.h>
#include <cstdint>

#define Bn 4
#define Tn 4096
#define Cn 1024
#define Hn 64

// fp16 scratch. g_q has 0.125*log2(e) folded (via Wq). g_vt is V TRANSPOSED [b][h][t].
__device__ __align__(16) __half g_q[Bn * Tn * Hn];
__device__ __align__(16) __half g_k[Bn * Tn * Hn];
__device__ __align__(16) __half g_vt[Bn * Hn * Tn];
__device__ __align__(16) __half g_wt[192 * 1024];   // W transposed fp16: [col][k]
// Split-KV partials: O in fp16, stats fp32. [e][b][qt][row][col] / [e][b][qt][row]
__device__ __align__(16) __half g_po[2 * 4 * 64 * 64 * 64];
__device__ float g_pm[2 * 4 * 64 * 64];
__device__ float g_pl[2 * 4 * 64 * 64];

__device__ __forceinline__ void mmah(float* c, const uint32_t* a, const uint32_t* b) {
    asm volatile(
        "mma.sync.aligned.m16n8k16.row.col.f32.f16.f16.f32 "
        "{%0,%1,%2,%3}, {%4,%5,%6,%7}, {%8,%9}, {%0,%1,%2,%3};"
        : "+f"(c[0]), "+f"(c[1]), "+f"(c[2]), "+f"(c[3])
        : "r"(a[0]), "r"(a[1]), "r"(a[2]), "r"(a[3]), "r"(b[0]), "r"(b[1]));
}

__device__ __forceinline__ void cpa16(void* dst, const void* src) {
    uint32_t d = (uint32_t)__cvta_generic_to_shared(dst);
    asm volatile("cp.async.cg.shared.global [%0], [%1], 16;" :: "r"(d), "l"(src));
}
#define CP_COMMIT() asm volatile("cp.async.commit_group;")
#define CP_WAIT0()  asm volatile("cp.async.wait_group 0;")

__device__ __forceinline__ void ldsm4(uint32_t& r0, uint32_t& r1, uint32_t& r2, uint32_t& r3,
                                      uint32_t a) {
    asm volatile("ldmatrix.sync.aligned.m8n8.x4.shared.b16 {%0,%1,%2,%3}, [%4];"
        : "=r"(r0), "=r"(r1), "=r"(r2), "=r"(r3) : "r"(a));
}

__device__ __forceinline__ uint32_t ex2h2(float a, float b) {
    __half2 h = __floats2half2_rn(a, b);
    uint32_t x = *reinterpret_cast<uint32_t*>(&h), d;
    asm("ex2.approx.f16x2 %0, %1;" : "=r"(d) : "r"(x));
    return d;
}

__device__ __forceinline__ uint32_t h2u(__half2 h) { return *reinterpret_cast<uint32_t*>(&h); }

// ---------------------------------------------------------------------------
// W pre-convert, transposed: g_wt[c][k]; c<64 -> Wq*QS, <128 -> Wk, <192 -> Wv.
// ---------------------------------------------------------------------------
__global__ void cvtw_kernel(const float* __restrict__ Wq,
                            const float* __restrict__ Wk,
                            const float* __restrict__ Wv)
{
    const float QS = 0.125f * 1.44269504088896f;
    int i = blockIdx.x * 256 + threadIdx.x;
    if (i >= 192 * 1024) return;
    int c = i >> 10, k = i & 1023;
    float v;
    if (c < 64)       v = Wq[k * 64 + c] * QS;
    else if (c < 128) v = Wk[k * 64 + (c - 64)];
    else              v = Wv[k * 64 + (c - 128)];
    g_wt[i] = __float2half_rn(v);
}

// ---------------------------------------------------------------------------
// Projection: y = x @ {Wq*s, Wk, Wv}, fp16 m16n8k16. M=16384, K=1024, N=192.
// K-chunk 64, double-buffered; all fragments via ldmatrix.x4.
// ---------------------------------------------------------------------------
#define PJ_SMEM ((2 * 4608 + 2 * 13824) * 2)

__global__ __launch_bounds__(256, 2) void proj_kernel(const float* __restrict__ x)
{
    extern __shared__ __half smh[];
    __half* xs = smh;               // 2 x [64][72]   (x rows, k cols)
    __half* ws = smh + 2 * 4608;    // 2 x [192][72]  (W cols as rows, k cols)

    const int tid = threadIdx.x;
    const int lane = tid & 31, wid = tid >> 5;
    const int m0 = blockIdx.x * 64;
    const int g = lane >> 2, q4 = lane & 3;

    // ldmatrix per-lane offsets (halves)
    const int bofs = (lane & 7) * 72 + (lane >> 3) * 8;                      // B: 1 n8 x 4 k8
    const int aofs = (((lane >> 3) & 1) * 8 + (lane & 7)) * 72 + (lane >> 4) * 8; // A: m16 x k16

    float acc[4][3][4];
#pragma unroll
    for (int mt = 0; mt < 4; mt++)
#pragma unroll
        for (int nt = 0; nt < 3; nt++)
#pragma unroll
            for (int i = 0; i < 4; i++) acc[mt][nt][i] = 0.f;

    // prologue: W chunk0 (192 rows x 64 halves = 8 x 16B per row)
#pragma unroll
    for (int i = 0; i < 6; i++) {
        int idx = tid + i * 256;
        int n = idx >> 3, cf = (idx & 7) * 8;
        cpa16(&ws[n * 72 + cf], &g_wt[n * 1024 + cf]);
    }
    CP_COMMIT();
    float4 xr[4];
#pragma unroll
    for (int i = 0; i < 4; i++) {
        int idx = tid + i * 256;
        int r = idx >> 4, c4 = (idx & 15) * 4;
        xr[i] = *(const float4*)&x[(size_t)(m0 + r) * Cn + c4];
    }
#pragma unroll
    for (int i = 0; i < 4; i++) {
        int idx = tid + i * 256;
        int r = idx >> 4, c4 = (idx & 15) * 4;
        uint2 u = make_uint2(h2u(__floats2half2_rn(xr[i].x, xr[i].y)),
                             h2u(__floats2half2_rn(xr[i].z, xr[i].w)));
        *(uint2*)&xs[r * 72 + c4] = u;
    }

    for (int j = 0; j < 16; j++) {
        __half* xsj = xs + (j & 1) * 4608;
        __half* wsj = ws + (j & 1) * 13824;
        CP_WAIT0();
        __syncthreads();
        if (j < 15) {
            int k0n = (j + 1) * 64;
            __half* wn = ws + ((j + 1) & 1) * 13824;
#pragma unroll
            for (int i = 0; i < 6; i++) {
                int idx = tid + i * 256;
                int n = idx >> 3, cf = (idx & 7) * 8;
                cpa16(&wn[n * 72 + cf], &g_wt[n * 1024 + k0n + cf]);
            }
            CP_COMMIT();
#pragma unroll
            for (int i = 0; i < 4; i++) {
                int idx = tid + i * 256;
                int r = idx >> 4, c4 = (idx & 15) * 4;
                xr[i] = *(const float4*)&x[(size_t)(m0 + r) * Cn + k0n + c4];
            }
        }

        const uint32_t xa = (uint32_t)__cvta_generic_to_shared(xsj);
        const uint32_t wa = (uint32_t)__cvta_generic_to_shared(wsj);
#pragma unroll
        for (int kg = 0; kg < 2; kg++) {
            uint32_t bf[3][4];
#pragma unroll
            for (int nt = 0; nt < 3; nt++)
                ldsm4(bf[nt][0], bf[nt][1], bf[nt][2], bf[nt][3],
                      wa + 2 * ((wid * 24 + nt * 8) * 72 + kg * 32 + bofs));
#pragma unroll
            for (int k16 = 0; k16 < 2; k16++) {
#pragma unroll
                for (int mt = 0; mt < 4; mt++) {
                    uint32_t a[4];
                    ldsm4(a[0], a[1], a[2], a[3],
                          xa + 2 * (mt * 16 * 72 + kg * 32 + k16 * 16 + aofs));
#pragma unroll
                    for (int nt = 0; nt < 3; nt++) {
                        uint32_t bb[2] = { bf[nt][2 * k16], bf[nt][2 * k16 + 1] };
                        mmah(acc[mt][nt], a, bb);
                    }
                }
            }
        }

        if (j < 15) {
            __half* xn = xs + ((j + 1) & 1) * 4608;
#pragma unroll
            for (int i = 0; i < 4; i++) {
                int idx = tid + i * 256;
                int r = idx >> 4, c4 = (idx & 15) * 4;
                uint2 u = make_uint2(h2u(__floats2half2_rn(xr[i].x, xr[i].y)),
                                     h2u(__floats2half2_rn(xr[i].z, xr[i].w)));
                *(uint2*)&xn[r * 72 + c4] = u;
            }
        }
    }

    const int bb = m0 >> 12, t0 = m0 & 4095;
#pragma unroll
    for (int mt = 0; mt < 4; mt++)
#pragma unroll
        for (int nt = 0; nt < 3; nt++) {
            int col = wid * 24 + nt * 8;
            if (col < 128) {
                __half* dst = (col < 64) ? g_q : g_k;
                int h = (col & 63) + 2 * q4;
                size_t r = (size_t)(m0 + mt * 16 + g) * 64 + h;
                *(__half2*)&dst[r] = __floats2half2_rn(acc[mt][nt][0], acc[mt][nt][1]);
                *(__half2*)&dst[r + 8 * 64] = __floats2half2_rn(acc[mt][nt][2], acc[mt][nt][3]);
            } else {
                int h = (col - 128) + 2 * q4;
                int tr = t0 + mt * 16 + g;
                __half* vp = &g_vt[((size_t)bb * 64 + h) * 4096 + tr];
                vp[0]        = __float2half_rn(acc[mt][nt][0]);
                vp[4096]     = __float2half_rn(acc[mt][nt][1]);
                vp[8]        = __float2half_rn(acc[mt][nt][2]);
                vp[4096 + 8] = __float2half_rn(acc[mt][nt][3]);
            }
        }
}

// ---------------------------------------------------------------------------
// Causal flash attention, fp16 m16n8k16, parity split-KV, per-warp softmax.
// Q fragments hoisted to registers; K/V fragments via ldmatrix.x4;
// P in registers; row sums via ones-MMA; exp via ex2.approx.f16x2.
// ---------------------------------------------------------------------------
#define AT_SMEM (5 * 4608 * 2)

__global__ __launch_bounds__(256, 2) void attn_kernel()
{
    extern __shared__ __half smh[];
    __half* ks = smh;                 // 2 x [64 key][72]
    __half* vt = smh + 2 * 4608;      // 2 x [64 h][72]  (V^T: [h][key])
    __half* qs = smh + 4 * 4608;      // [64 row][72]
    float* Om  = (float*)vt;          // epilogue reuse [64][64]
    float* m1a = (float*)ks;          // epilogue reuse [64]
    float* l1a = m1a + 64;

    const int tid = threadIdx.x, lane = tid & 31, wid = tid >> 5;
    const int wc = wid >> 2, wr = wid & 3;
    const int g = lane >> 2, q4 = lane & 3;
    const int mrow = wr * 16 + g;
    const int e = blockIdx.x & 1, p = blockIdx.x >> 1;
    const int by = blockIdx.y;
    const size_t base = (size_t)by * Tn * Hn;
    const uint32_t ONES = 0x3C003C00u;
    const uint32_t onesb[2] = { ONES, ONES };

    const int mt8 = lane >> 3, rw = lane & 7;
    const int koff = (wc * 32 + (mt8 >> 1) * 8 + rw) * 72 + (mt8 & 1) * 8;
    const int voff = ((mt8 >> 1) * 8 + rw) * 72 + wc * 32 + (mt8 & 1) * 8;
    const int qoff = (wr * 16 + (mt8 & 1) * 8 + rw) * 72 + (mt8 >> 1) * 8;

    for (int pass = 0; pass < 2; pass++) {
        const int qt = pass ? 63 - p : p;

#pragma unroll
        for (int i = 0; i < 2; i++) {
            int idx = tid + i * 256;
            int r = idx >> 3, cf = (idx & 7) * 8;
            cpa16(&qs[r * 72 + cf], &g_q[base + (size_t)(qt * 64 + r) * 64 + cf]);
        }
        if (e <= qt) {
#pragma unroll
            for (int i = 0; i < 2; i++) {
                int idx = tid + i * 256;
                int r = idx >> 3, cf = (idx & 7) * 8;
                cpa16(&ks[r * 72 + cf], &g_k[base + (size_t)(e * 64 + r) * 64 + cf]);
                cpa16(&vt[r * 72 + cf], &g_vt[((size_t)by * 64 + r) * 4096 + e * 64 + cf]);
            }
        }
        CP_COMMIT();
        CP_WAIT0();
        __syncthreads();

        uint32_t qa[4][4];
        {
            uint32_t qsa = (uint32_t)__cvta_generic_to_shared(qs) + 2 * qoff;
#pragma unroll
            for (int k16 = 0; k16 < 4; k16++)
                ldsm4(qa[k16][0], qa[k16][1], qa[k16][2], qa[k16][3], qsa + k16 * 32);
        }

        float o[8][4], ol[4];
#pragma unroll
        for (int nt = 0; nt < 8; nt++)
#pragma unroll
            for (int i = 0; i < 4; i++) o[nt][i] = 0.f;
#pragma unroll
        for (int i = 0; i < 4; i++) ol[i] = 0.f;
        float mA = -1e30f, mB = -1e30f;

        int t = 0;
        for (int j = e; j <= qt; j += 2, t++) {
            __half* kb = ks + (t & 1) * 4608;
            __half* vb = vt + (t & 1) * 4608;
            CP_WAIT0();
            __syncthreads();
            if (j + 2 <= qt) {
                __half* kn = ks + ((t + 1) & 1) * 4608;
                __half* vn = vt + ((t + 1) & 1) * 4608;
#pragma unroll
                for (int i = 0; i < 2; i++) {
                    int idx = tid + i * 256;
                    int r = idx >> 3, cf = (idx & 7) * 8;
                    cpa16(&kn[r * 72 + cf], &g_k[base + (size_t)((j + 2) * 64 + r) * 64 + cf]);
                    cpa16(&vn[r * 72 + cf], &g_vt[((size_t)by * 64 + r) * 4096 + (j + 2) * 64 + cf]);
                }
                CP_COMMIT();
            }

            const uint32_t kba = (uint32_t)__cvta_generic_to_shared(kb) + 2 * koff;
            const uint32_t vba = (uint32_t)__cvta_generic_to_shared(vb) + 2 * voff;

            float s[4][4];
#pragma unroll
            for (int nt = 0; nt < 4; nt++)
#pragma unroll
                for (int i = 0; i < 4; i++) s[nt][i] = 0.f;
#pragma unroll
            for (int k16 = 0; k16 < 4; k16++) {
#pragma unroll
                for (int a2 = 0; a2 < 2; a2++) {
                    uint32_t b0, b1, b2, b3;
                    ldsm4(b0, b1, b2, b3, kba + 2 * (a2 * 16 * 72) + k16 * 32);
                    uint32_t bb0[2] = { b0, b1 }, bb1[2] = { b2, b3 };
                    mmah(s[2 * a2],     qa[k16], bb0);
                    mmah(s[2 * a2 + 1], qa[k16], bb1);
                }
            }
            if (j == qt) {
#pragma unroll
                for (int nt = 0; nt < 4; nt++) {
                    int c0 = wc * 32 + nt * 8 + 2 * q4;
                    if (c0 > mrow)         s[nt][0] = -1e30f;
                    if (c0 + 1 > mrow)     s[nt][1] = -1e30f;
                    if (c0 > mrow + 8)     s[nt][2] = -1e30f;
                    if (c0 + 1 > mrow + 8) s[nt][3] = -1e30f;
                }
            }

            float mx0 = -1e30f, mx1 = -1e30f;
#pragma unroll
            for (int nt = 0; nt < 4; nt++) {
                mx0 = fmaxf(mx0, fmaxf(s[nt][0], s[nt][1]));
                mx1 = fmaxf(mx1, fmaxf(s[nt][2], s[nt][3]));
            }
            __half2 hmx = __floats2half2_rn(mx0, mx1);
            uint32_t um = *reinterpret_cast<uint32_t*>(&hmx);
            uint32_t um1 = __shfl_xor_sync(~0u, um, 1);
            hmx = __hmax2(hmx, *reinterpret_cast<__half2*>(&um1));
            um = *reinterpret_cast<uint32_t*>(&hmx);
            uint32_t um2 = __shfl_xor_sync(~0u, um, 2);
            hmx = __hmax2(hmx, *reinterpret_cast<__half2*>(&um2));
            float2 mxf = __half22float2(hmx);
            float mn0 = fmaxf(mA, mxf.x), mn1 = fmaxf(mB, mxf.y);
            float corr0 = exp2f(mA - mn0), corr1 = exp2f(mB - mn1);
            mA = mn0; mB = mn1;

            uint32_t ph0[4], ph1[4];
#pragma unroll
            for (int nt = 0; nt < 4; nt++) {
                ph0[nt] = ex2h2(s[nt][0] - mn0, s[nt][1] - mn0);
                ph1[nt] = ex2h2(s[nt][2] - mn1, s[nt][3] - mn1);
            }

#pragma unroll
            for (int nt = 0; nt < 8; nt++) {
                o[nt][0] *= corr0; o[nt][1] *= corr0;
                o[nt][2] *= corr1; o[nt][3] *= corr1;
            }
            ol[0] *= corr0; ol[1] *= corr0; ol[2] *= corr1; ol[3] *= corr1;

#pragma unroll
            for (int kg = 0; kg < 2; kg++) {
                uint32_t a[4] = { ph0[2 * kg], ph1[2 * kg], ph0[2 * kg + 1], ph1[2 * kg + 1] };
                mmah(ol, a, onesb);
#pragma unroll
                for (int vg = 0; vg < 4; vg++) {
                    uint32_t b0, b1, b2, b3;
                    ldsm4(b0, b1, b2, b3, vba + 2 * (vg * 16 * 72) + kg * 32);
                    uint32_t bb0[2] = { b0, b1 }, bb1[2] = { b2, b3 };
                    mmah(o[2 * vg],     a, bb0);
                    mmah(o[2 * vg + 1], a, bb1);
                }
            }
        }
        float lA = ol[0], lB = ol[2];

        __syncthreads();
        if (wc == 1) {
            if (q4 == 0) {
                m1a[mrow] = mA; m1a[mrow + 8] = mB;
                l1a[mrow] = lA; l1a[mrow + 8] = lB;
            }
#pragma unroll
            for (int nt = 0; nt < 8; nt++) {
                int cb = nt * 8 + 2 * q4;
                *(float2*)&Om[mrow * 64 + cb]       = make_float2(o[nt][0], o[nt][1]);
                *(float2*)&Om[(mrow + 8) * 64 + cb] = make_float2(o[nt][2], o[nt][3]);
            }
        }
        __syncthreads();
        if (wc == 0) {
            float m1w = m1a[mrow], l1w = l1a[mrow];
            float m1x = m1a[mrow + 8], l1x = l1a[mrow + 8];
            float mf0 = fmaxf(mA, m1w), mf1 = fmaxf(mB, m1x);
            float cA0 = exp2f(mA - mf0), cB0 = exp2f(m1w - mf0);
            float cA1 = exp2f(mB - mf1), cB1 = exp2f(m1x - mf1);
            float lf0 = lA * cA0 + l1w * cB0;
            float lf1 = lB * cA1 + l1x * cB1;
            int mlb = ((e * 4 + by) * 64 + qt) * 64;
            if (q4 == 0) {
                g_pm[mlb + mrow] = mf0; g_pm[mlb + mrow + 8] = mf1;
                g_pl[mlb + mrow] = lf0; g_pl[mlb + mrow + 8] = lf1;
            }
            size_t pob = ((size_t)(e * 4 + by) * 64 + qt) * 4096;
#pragma unroll
            for (int nt = 0; nt < 8; nt++) {
                int cb = nt * 8 + 2 * q4;
                float2 v0 = *(float2*)&Om[mrow * 64 + cb];
                *(__half2*)&g_po[pob + mrow * 64 + cb] =
                    __floats2half2_rn(o[nt][0] * cA0 + v0.x * cB0, o[nt][1] * cA0 + v0.y * cB0);
                float2 v1 = *(float2*)&Om[(mrow + 8) * 64 + cb];
                *(__half2*)&g_po[pob + (mrow + 8) * 64 + cb] =
                    __floats2half2_rn(o[nt][2] * cA1 + v1.x * cB1, o[nt][3] * cA1 + v1.y * cB1);
            }
        }
        __syncthreads();
    }
}

// ---------------------------------------------------------------------------
// Merge the two parity partials -> final normalized output. 8 cols/thread.
// ---------------------------------------------------------------------------
__global__ void merge_kernel(float* __restrict__ out)
{
    int idx = blockIdx.x * 256 + threadIdx.x;      // < 4*64*64*8 = 131072
    int c8  = idx & 7;
    int row = (idx >> 3) & 63;
    int qt  = (idx >> 9) & 63;
    int b   = idx >> 15;
    int mlb = (b * 64 + qt) * 64 + row;
    float m0 = g_pm[mlb],         l0 = g_pl[mlb];
    float m1 = g_pm[mlb + 16384], l1 = g_pl[mlb + 16384];
    float mf = fmaxf(m0, m1);
    float c0 = exp2f(m0 - mf), c1 = exp2f(m1 - mf);
    float inv = 1.f / (l0 * c0 + l1 * c1);
    size_t p0 = ((size_t)(b * 64) + qt) * 4096 + row * 64 + c8 * 8;
    uint4 ua = *(const uint4*)&g_po[p0];
    uint4 ub = *(const uint4*)&g_po[p0 + 1048576];
    float2 a0 = __half22float2(*(__half2*)&ua.x), b0 = __half22float2(*(__half2*)&ub.x);
    float2 a1 = __half22float2(*(__half2*)&ua.y), b1 = __half22float2(*(__half2*)&ub.y);
    float2 a2 = __half22float2(*(__half2*)&ua.z), b2 = __half22float2(*(__half2*)&ub.z);
    float2 a3 = __half22float2(*(__half2*)&ua.w), b3 = __half22float2(*(__half2*)&ub.w);
    size_t ob = ((size_t)b * 4096 + qt * 64 + row) * 64 + c8 * 8;
    float4 r0 = make_float4((a0.x * c0 + b0.x * c1) * inv, (a0.y * c0 + b0.y * c1) * inv,
                            (a1.x * c0 + b1.x * c1) * inv, (a1.y * c0 + b1.y * c1) * inv);
    float4 r1 = make_float4((a2.x * c0 + b2.x * c1) * inv, (a2.y * c0 + b2.y * c1) * inv,
                            (a3.x * c0 + b3.x * c1) * inv, (a3.y * c0 + b3.y * c1) * inv);
    *(float4*)&out[ob]     = r0;
    *(float4*)&out[ob + 4] = r1;
}

// ---------------------------------------------------------------------------
extern "C" void kernel_launch(void* const* d_in, const int* in_sizes, int n_in,
                              void* d_out, int out_size)
{
    const float* x  = (const float*)d_in[0];
    const float* Wk = (const float*)d_in[1];
    const float* Wq = (const float*)d_in[2];
    const float* Wv = (const float*)d_in[3];
    float* out = (float*)d_out;

    cudaFuncSetAttribute(proj_kernel, cudaFuncAttributeMaxDynamicSharedMemorySize, PJ_SMEM);
    cudaFuncSetAttribute(attn_kernel, cudaFuncAttributeMaxDynamicSharedMemorySize, AT_SMEM);

    cvtw_kernel<<<768, 256>>>(Wq, Wk, Wv);
    proj_kernel<<<(Bn * Tn) / 64, 256, PJ_SMEM>>>(x);
    attn_kernel<<<dim3(64, Bn), 256, AT_SMEM>>>();
    merge_kernel<<<512, 256>>>(out);
}